// round 11
// baseline (speedup 1.0000x reference)
#include <cuda_runtime.h>
#include <cuda_bf16.h>
#include <cstdint>

#define NB 32
#define NV 512
#define ND 256
#define NL 4
#define NH 8
#define NDH 64
#define NHD 512
#define NMLP 1024
#define NRES 128
#define MTOK (NB*NV)
#define KVN (NL*NH*NDH)

__device__ float g_att[MTOK*NHD];
__device__ float g_scores[NB*NH*NV*NV];
__device__ float g_ctx[MTOK*NHD];
__device__ float g_logit[MTOK*NRES];
__device__ __nv_bfloat16 g_qt0[MTOK*NHD], g_qt1[MTOK*NHD], g_qt2[MTOK*NHD];
__device__ __nv_bfloat16 g_am0[MTOK*NMLP], g_am1[MTOK*NMLP], g_am2[MTOK*NMLP];
__device__ __nv_bfloat16 g_fs0[MTOK*NMLP], g_fs1[MTOK*NMLP], g_fs2[MTOK*NMLP];
__device__ __nv_bfloat16 g_kt0[MTOK*KVN], g_kt1[MTOK*KVN], g_kt2[MTOK*KVN];
__device__ __nv_bfloat16 g_vt0[MTOK*KVN], g_vt1[MTOK*KVN], g_vt2[MTOK*KVN];
__device__ __nv_bfloat16 g_ps0[NB*NH*NV*NV], g_ps1[NB*NH*NV*NV], g_ps2[NB*NH*NV*NV];
#define BS_TOT 9633792
__device__ __nv_bfloat16 g_bs0[BS_TOT], g_bs1[BS_TOT], g_bs2[BS_TOT];
#define OFF_SH 0
#define OFF_K  131072
#define OFF_V  655360
#define OFF_W1(l) (1179648 + (l)*2097152)
#define OFF_W2(l) (OFF_W1(l) + 524288)
#define OFF_W3(l) (OFF_W2(l) + 1048576)
#define OFF_WD 9568256

__device__ __forceinline__ void split3(float v, __nv_bfloat16& a, __nv_bfloat16& b, __nv_bfloat16& c)
{
    __nv_bfloat16 h0 = __float2bfloat16(v);
    float r1 = v - __bfloat162float(h0);
    __nv_bfloat16 h1 = __float2bfloat16(r1);
    float r2 = r1 - __bfloat162float(h1);
    a = h0; b = h1; c = __float2bfloat16(r2);
}
__global__ void split3_kernel(const float* __restrict__ x, __nv_bfloat16* __restrict__ o0,
    __nv_bfloat16* __restrict__ o1, __nv_bfloat16* __restrict__ o2, int n)
{
    int i = blockIdx.x*256 + threadIdx.x;
    if (i >= n) return;
    split3(x[i], o0[i], o1[i], o2[i]);
}
// Tiled transpose-split: per batch z, in = w[z] row-major [R,C]; out[z][c*R + r].
// Coalesced reads and writes; 33-pitch smem kills bank conflicts.
__global__ __launch_bounds__(256) void splitT_kernel(
    const float* __restrict__ w, __nv_bfloat16* __restrict__ o0,
    __nv_bfloat16* __restrict__ o1, __nv_bfloat16* __restrict__ o2, int R, int C)
{
    __shared__ float tile[32][33];
    int z = blockIdx.z;
    const float* wz = w + (size_t)z * R * C;
    size_t ob = (size_t)z * R * C;
    int c0 = blockIdx.x * 32, r0 = blockIdx.y * 32;
    int tx = threadIdx.x & 31, ty = threadIdx.x >> 5;
#pragma unroll
    for (int j = 0; j < 4; j++) {
        int r = ty * 4 + j;
        tile[r][tx] = wz[(size_t)(r0 + r) * C + c0 + tx];
    }
    __syncthreads();
#pragma unroll
    for (int j = 0; j < 4; j++) {
        int rr = ty * 4 + j;
        size_t g = ob + (size_t)(c0 + rr) * R + r0 + tx;
        split3(tile[tx][rr], o0[g], o1[g], o2[g]);
    }
}

// ===== common MMA helpers =====
__device__ __forceinline__ uint32_t s2u(const void* p) {
    uint32_t a;
    asm("{.reg .u64 t; cvta.to.shared.u64 t, %1; cvt.u32.u64 %0, t;}" : "=r"(a) : "l"(p));
    return a;
}
__device__ __forceinline__ void ldsm4(uint32_t* r, uint32_t addr) {
    asm volatile("ldmatrix.sync.aligned.m8n8.x4.shared.b16 {%0,%1,%2,%3},[%4];"
        : "=r"(r[0]), "=r"(r[1]), "=r"(r[2]), "=r"(r[3]) : "r"(addr));
}
__device__ __forceinline__ void ldsm4t(uint32_t* r, uint32_t addr) {
    asm volatile("ldmatrix.sync.aligned.m8n8.x4.trans.shared.b16 {%0,%1,%2,%3},[%4];"
        : "=r"(r[0]), "=r"(r[1]), "=r"(r[2]), "=r"(r[3]) : "r"(addr));
}
__device__ __forceinline__ void mma16816(float* d, const uint32_t* a, const uint32_t* b) {
    asm volatile("mma.sync.aligned.m16n8k16.row.col.f32.bf16.bf16.f32 "
        "{%0,%1,%2,%3},{%4,%5,%6,%7},{%8,%9},{%0,%1,%2,%3};"
        : "+f"(d[0]), "+f"(d[1]), "+f"(d[2]), "+f"(d[3])
        : "r"(a[0]), "r"(a[1]), "r"(a[2]), "r"(a[3]), "r"(b[0]), "r"(b[1]));
}
__device__ __forceinline__ uint32_t swq(int r, int q) { return (uint32_t)(q ^ ((r + (r >> 2)) & 3)); }

// ===== dense mma_gemm =====
#define MG_STAGE 49152
#define MG_SMEM  (2*MG_STAGE)
__global__ __launch_bounds__(256) void mma_gemm(
    const __nv_bfloat16* __restrict__ A0, const __nv_bfloat16* __restrict__ A1,
    const __nv_bfloat16* __restrict__ A2, const __nv_bfloat16* __restrict__ B0,
    const __nv_bfloat16* __restrict__ B1, const __nv_bfloat16* __restrict__ B2,
    float* __restrict__ C, const float* __restrict__ bias,
    __nv_bfloat16* __restrict__ o0, __nv_bfloat16* __restrict__ o1,
    __nv_bfloat16* __restrict__ o2, int K, int N, int relu)
{
    extern __shared__ __align__(128) char smem[];
    uint32_t sbase = s2u(smem);
    int tid = threadIdx.x, lane = tid & 31, wid = tid >> 5;
    int tm = blockIdx.y * 128, tn = blockIdx.x * 128;
    int wm = (wid >> 2) * 64, wn = (wid & 3) * 32;
    const __nv_bfloat16* Ap[3] = {A0, A1, A2};
    const __nv_bfloat16* Bp[3] = {B0, B1, B2};
    float acc[4][4][4];
#pragma unroll
    for (int a = 0; a < 4; a++)
#pragma unroll
        for (int b = 0; b < 4; b++)
#pragma unroll
            for (int c = 0; c < 4; c++) acc[a][b][c] = 0.f;
    auto load = [&](int c) {
        int kc = c * 32;
        uint32_t sb = sbase + (c & 1) * MG_STAGE;
#pragma unroll
        for (int i = 0; i < 12; i++) {
            int f = tid + i * 256;
            int comp = f >> 9, idx = f & 511;
            int r = idx >> 2, q = idx & 3;
            const __nv_bfloat16* src = (comp < 3)
                ? Ap[comp] + (size_t)(tm + r) * K + kc + q * 8
                : Bp[comp - 3] + (size_t)(tn + r) * K + kc + q * 8;
            uint32_t dst = sb + comp * 8192 + r * 64 + (swq(r, q) << 4);
            asm volatile("cp.async.cg.shared.global [%0],[%1],16;" :: "r"(dst), "l"(src));
        }
        asm volatile("cp.async.commit_group;" ::: "memory");
    };
    int nc = K >> 5;
    load(0);
    for (int c = 0; c < nc; c++) {
        if (c + 1 < nc) { load(c + 1); asm volatile("cp.async.wait_group 1;" ::: "memory"); }
        else asm volatile("cp.async.wait_group 0;" ::: "memory");
        __syncthreads();
        uint32_t sb = sbase + (c & 1) * MG_STAGE;
#pragma unroll
        for (int ks = 0; ks < 2; ks++) {
            uint32_t bf[3][8];
#pragma unroll
            for (int bc = 0; bc < 3; bc++)
#pragma unroll
                for (int h = 0; h < 2; h++) {
                    int mat = lane >> 3;
                    int n = wn + h * 16 + (mat >> 1) * 8 + (lane & 7);
                    int kq = ks * 2 + (mat & 1);
                    ldsm4(&bf[bc][h * 4], sb + (3 + bc) * 8192 + n * 64 + (swq(n, kq) << 4));
                }
#pragma unroll
            for (int ac = 0; ac < 3; ac++) {
                uint32_t af[16];
#pragma unroll
                for (int mt = 0; mt < 4; mt++) {
                    int mat = lane >> 3;
                    int row = wm + mt * 16 + (mat & 1) * 8 + (lane & 7);
                    int kq = ks * 2 + (mat >> 1);
                    ldsm4(&af[mt * 4], sb + ac * 8192 + row * 64 + (swq(row, kq) << 4));
                }
#pragma unroll
                for (int bc = 0; bc < 3 - ac; bc++)
#pragma unroll
                    for (int mt = 0; mt < 4; mt++)
#pragma unroll
                        for (int nt = 0; nt < 4; nt++)
                            mma16816(acc[mt][nt], &af[mt * 4],
                                     &bf[bc][(nt >> 1) * 4 + (nt & 1) * 2]);
            }
        }
        __syncthreads();
    }
    int r0 = lane >> 2, c0 = (lane & 3) * 2;
    float* Cs = (float*)smem;
#pragma unroll
    for (int mt = 0; mt < 4; mt++)
#pragma unroll
        for (int i = 0; i < 2; i++) {
            int rl = wm + mt * 16 + r0 + i * 8;
            int row = tm + rl;
#pragma unroll
            for (int nt = 0; nt < 4; nt++) {
                int cl = wn + nt * 8 + c0;
                int col = tn + cl;
                float v0 = acc[mt][nt][i * 2 + 0] + bias[col];
                float v1 = acc[mt][nt][i * 2 + 1] + bias[col + 1];
                if (relu) { v0 = fmaxf(v0, 0.f); v1 = fmaxf(v1, 0.f); }
                if (C) *(float2*)&C[(size_t)row * N + col] = make_float2(v0, v1);
                if (o0) { Cs[rl * 132 + cl] = v0; Cs[rl * 132 + cl + 1] = v1; }
            }
        }
    if (o0) {
        __syncthreads();
#pragma unroll 1
        for (int it = 0; it < 64; it++) {
            int idx = it * 256 + tid;
            int r = idx >> 7, cl = idx & 127;
            size_t g = (size_t)(tm + r) * N + tn + cl;
            split3(Cs[r * 132 + cl], o0[g], o1[g], o2[g]);
        }
    }
}

// ===== batched scores MMA =====
#define SC_SMEM (6*16384)
__global__ __launch_bounds__(256) void mma_scores(
    const __nv_bfloat16* __restrict__ Q0, const __nv_bfloat16* __restrict__ Q1,
    const __nv_bfloat16* __restrict__ Q2, const __nv_bfloat16* __restrict__ K0,
    const __nv_bfloat16* __restrict__ K1, const __nv_bfloat16* __restrict__ K2,
    float* __restrict__ sc, int l)
{
    extern __shared__ __align__(128) char smem[];
    uint32_t sbase = s2u(smem);
    int tid = threadIdx.x, lane = tid & 31, wid = tid >> 5;
    int z = blockIdx.z, b = z >> 3, h = z & 7;
    int tm = blockIdx.y * 128, tn = blockIdx.x * 128;
    int wm = (wid >> 2) * 64, wn = (wid & 3) * 32;
    const __nv_bfloat16* Qp[3] = {Q0, Q1, Q2};
    const __nv_bfloat16* Kp[3] = {K0, K1, K2};
    size_t qoff = (size_t)(b * 512 + tm) * NHD + h * 64;
    size_t koff = (size_t)(b * 512 + tn) * KVN + l * 512 + h * 64;
#pragma unroll
    for (int i = 0; i < 24; i++) {
        int f = tid + i * 256;
        int comp = f >> 10, idx = f & 1023;
        int r = idx >> 3, q = idx & 7;
        const __nv_bfloat16* src = (comp < 3)
            ? Qp[comp] + qoff + (size_t)r * NHD + q * 8
            : Kp[comp - 3] + koff + (size_t)r * KVN + q * 8;
        uint32_t dst = sbase + comp * 16384 + r * 128 + ((uint32_t)(q ^ (r & 7)) << 4);
        asm volatile("cp.async.cg.shared.global [%0],[%1],16;" :: "r"(dst), "l"(src));
    }
    asm volatile("cp.async.commit_group;" ::: "memory");
    asm volatile("cp.async.wait_group 0;" ::: "memory");
    __syncthreads();
    float acc[4][4][4];
#pragma unroll
    for (int a = 0; a < 4; a++)
#pragma unroll
        for (int bb = 0; bb < 4; bb++)
#pragma unroll
            for (int c = 0; c < 4; c++) acc[a][bb][c] = 0.f;
#pragma unroll
    for (int ks = 0; ks < 4; ks++) {
        uint32_t bf[3][8];
#pragma unroll
        for (int bc = 0; bc < 3; bc++)
#pragma unroll
            for (int hh = 0; hh < 2; hh++) {
                int mat = lane >> 3;
                int n = wn + hh * 16 + (mat >> 1) * 8 + (lane & 7);
                int kq = ks * 2 + (mat & 1);
                ldsm4(&bf[bc][hh * 4], sbase + (3 + bc) * 16384 + n * 128 + ((uint32_t)(kq ^ (n & 7)) << 4));
            }
#pragma unroll
        for (int ac = 0; ac < 3; ac++) {
            uint32_t af[16];
#pragma unroll
            for (int mt = 0; mt < 4; mt++) {
                int mat = lane >> 3;
                int row = wm + mt * 16 + (mat & 1) * 8 + (lane & 7);
                int kq = ks * 2 + (mat >> 1);
                ldsm4(&af[mt * 4], sbase + ac * 16384 + row * 128 + ((uint32_t)(kq ^ (row & 7)) << 4));
            }
#pragma unroll
            for (int bc = 0; bc < 3 - ac; bc++)
#pragma unroll
                for (int mt = 0; mt < 4; mt++)
#pragma unroll
                    for (int nt = 0; nt < 4; nt++)
                        mma16816(acc[mt][nt], &af[mt * 4], &bf[bc][(nt >> 1) * 4 + (nt & 1) * 2]);
        }
    }
    int r0 = lane >> 2, c0 = (lane & 3) * 2;
    float* scz = sc + (size_t)z * NV * NV;
#pragma unroll
    for (int mt = 0; mt < 4; mt++)
#pragma unroll
        for (int i = 0; i < 2; i++) {
            int row = tm + wm + mt * 16 + r0 + i * 8;
#pragma unroll
            for (int nt = 0; nt < 4; nt++) {
                int col = tn + wn + nt * 8 + c0;
                *(float2*)&scz[(size_t)row * NV + col] = make_float2(
                    acc[mt][nt][i * 2 + 0] * 0.125f, acc[mt][nt][i * 2 + 1] * 0.125f);
            }
        }
}

// ===== batched ctx MMA =====
#define CT_STAGE 73728
#define CT_SMEM (2*CT_STAGE)
__global__ __launch_bounds__(256) void mma_ctx(
    const __nv_bfloat16* __restrict__ P0, const __nv_bfloat16* __restrict__ P1,
    const __nv_bfloat16* __restrict__ P2, const __nv_bfloat16* __restrict__ V0,
    const __nv_bfloat16* __restrict__ V1, const __nv_bfloat16* __restrict__ V2,
    float* __restrict__ C, int l)
{
    extern __shared__ __align__(128) char smem[];
    uint32_t sbase = s2u(smem);
    int tid = threadIdx.x, lane = tid & 31, wid = tid >> 5;
    int z = blockIdx.z, b = z >> 3, h = z & 7;
    int tm = blockIdx.y * 128;
    int wm = (wid >> 1) * 32, wn = (wid & 1) * 32;
    const __nv_bfloat16* Pp[3] = {P0, P1, P2};
    const __nv_bfloat16* Vp[3] = {V0, V1, V2};
    size_t poff = ((size_t)z * 512 + tm) * 512;
    size_t voff = (size_t)(b * 512) * KVN + l * 512 + h * 64;
    float acc[2][4][4];
#pragma unroll
    for (int a = 0; a < 2; a++)
#pragma unroll
        for (int bb = 0; bb < 4; bb++)
#pragma unroll
            for (int c = 0; c < 4; c++) acc[a][bb][c] = 0.f;
    auto load = [&](int c) {
        int kc = c * 64;
        uint32_t sb = sbase + (c & 1) * CT_STAGE;
#pragma unroll
        for (int i = 0; i < 18; i++) {
            int f = tid + i * 256;
            if (f < 3072) {
                int comp = f >> 10, idx = f & 1023;
                int r = idx >> 3, q = idx & 7;
                const __nv_bfloat16* src = Pp[comp] + poff + (size_t)r * 512 + kc + q * 8;
                uint32_t dst = sb + comp * 16384 + r * 128 + ((uint32_t)(q ^ (r & 7)) << 4);
                asm volatile("cp.async.cg.shared.global [%0],[%1],16;" :: "r"(dst), "l"(src));
            } else {
                int g = f - 3072;
                int comp = g >> 9, idx = g & 511;
                int kr = idx >> 3, q = idx & 7;
                const __nv_bfloat16* src = Vp[comp] + voff + (size_t)(kc + kr) * KVN + q * 8;
                uint32_t dst = sb + 49152 + comp * 8192 + kr * 128 + ((uint32_t)(q ^ (kr & 7)) << 4);
                asm volatile("cp.async.cg.shared.global [%0],[%1],16;" :: "r"(dst), "l"(src));
            }
        }
        asm volatile("cp.async.commit_group;" ::: "memory");
    };
    load(0);
    for (int c = 0; c < 8; c++) {
        if (c + 1 < 8) { load(c + 1); asm volatile("cp.async.wait_group 1;" ::: "memory"); }
        else asm volatile("cp.async.wait_group 0;" ::: "memory");
        __syncthreads();
        uint32_t sb = sbase + (c & 1) * CT_STAGE;
#pragma unroll
        for (int ks = 0; ks < 4; ks++) {
            uint32_t bf[3][8];
#pragma unroll
            for (int bc = 0; bc < 3; bc++)
#pragma unroll
                for (int j = 0; j < 2; j++) {
                    int krow = ks * 16 + (lane & 15);
                    int qn = ((wn + j * 16) >> 3) + (lane >> 4);
                    ldsm4t(&bf[bc][j * 4],
                           sb + 49152 + bc * 8192 + krow * 128 + ((uint32_t)(qn ^ (krow & 7)) << 4));
                }
#pragma unroll
            for (int ac = 0; ac < 3; ac++) {
                uint32_t af[8];
#pragma unroll
                for (int mt = 0; mt < 2; mt++) {
                    int mat = lane >> 3;
                    int row = wm + mt * 16 + (mat & 1) * 8 + (lane & 7);
                    int kq = ks * 2 + (mat >> 1);
                    ldsm4(&af[mt * 4], sb + ac * 16384 + row * 128 + ((uint32_t)(kq ^ (row & 7)) << 4));
                }
#pragma unroll
                for (int bc = 0; bc < 3 - ac; bc++)
#pragma unroll
                    for (int mt = 0; mt < 2; mt++)
#pragma unroll
                        for (int nt = 0; nt < 4; nt++)
                            mma16816(acc[mt][nt], &af[mt * 4], &bf[bc][(nt >> 1) * 4 + (nt & 1) * 2]);
            }
        }
        __syncthreads();
    }
    int r0 = lane >> 2, c0 = (lane & 3) * 2;
#pragma unroll
    for (int mt = 0; mt < 2; mt++)
#pragma unroll
        for (int i = 0; i < 2; i++) {
            int row = b * 512 + tm + wm + mt * 16 + r0 + i * 8;
#pragma unroll
            for (int nt = 0; nt < 4; nt++) {
                int col = h * 64 + wn + nt * 8 + c0;
                *(float2*)&C[(size_t)row * NHD + col] =
                    make_float2(acc[mt][nt][i * 2 + 0], acc[mt][nt][i * 2 + 1]);
            }
        }
}

// ===== softmax (emits bf16 splits of probs) =====
__global__ __launch_bounds__(256) void softmax512_split(
    const float* __restrict__ x, __nv_bfloat16* __restrict__ p0,
    __nv_bfloat16* __restrict__ p1, __nv_bfloat16* __restrict__ p2, int nrows)
{
    int gw = (blockIdx.x*256 + threadIdx.x) >> 5;
    if (gw >= nrows) return;
    int lane = threadIdx.x & 31;
    const float* row = x + (size_t)gw*512;
    float v[16], m = -3.4e38f;
#pragma unroll
    for (int i=0;i<16;i++){ v[i]=row[lane+32*i]; m=fmaxf(m,v[i]); }
#pragma unroll
    for (int o=16;o;o>>=1) m = fmaxf(m, __shfl_xor_sync(0xffffffffu,m,o));
    float s = 0.f;
#pragma unroll
    for (int i=0;i<16;i++){ v[i]=expf(v[i]-m); s+=v[i]; }
#pragma unroll
    for (int o=16;o;o>>=1) s += __shfl_xor_sync(0xffffffffu,s,o);
    float inv = 1.f/s;
#pragma unroll
    for (int i=0;i<16;i++) {
        size_t idx = (size_t)gw*512 + lane + 32*i;
        split3(v[i]*inv, p0[idx], p1[idx], p2[idx]);
    }
}

// ===== add + layernorm, emits bf16 splits =====
__global__ __launch_bounds__(256) void add_ln_kernel(
    float* __restrict__ att, const float* __restrict__ d,
    const float* __restrict__ g, const float* __restrict__ b, int nrows,
    __nv_bfloat16* __restrict__ o0, __nv_bfloat16* __restrict__ o1,
    __nv_bfloat16* __restrict__ o2)
{
    int gw = (blockIdx.x*256 + threadIdx.x) >> 5;
    if (gw >= nrows) return;
    int lane = threadIdx.x & 31;
    float* row = att + (size_t)gw*512;
    const float* dr = d + (size_t)gw*512;
    float v[16], s = 0.f;
#pragma unroll
    for (int i=0;i<16;i++){ v[i]=row[lane+32*i]+dr[lane+32*i]; s+=v[i]; }
#pragma unroll
    for (int o=16;o;o>>=1) s += __shfl_xor_sync(0xffffffffu,s,o);
    float mean = s*(1.f/512.f), q = 0.f;
#pragma unroll
    for (int i=0;i<16;i++){ float e=v[i]-mean; q+=e*e; }
#pragma unroll
    for (int o=16;o;o>>=1) q += __shfl_xor_sync(0xffffffffu,q,o);
    float inv = rsqrtf(q*(1.f/512.f) + 1e-5f);
#pragma unroll
    for (int i=0;i<16;i++){
        int c = lane+32*i;
        float val = (v[i]-mean)*inv*g[c]+b[c];
        row[c] = val;
        size_t idx = (size_t)gw*512 + c;
        split3(val, o0[idx], o1[idx], o2[idx]);
    }
}

// ===== sampling: argmax(gumbel+L) == argmin((-log u) * exp(-L)) =====
__device__ __forceinline__ void tf2x32(uint32_t k0, uint32_t k1, uint32_t x0, uint32_t x1,
                                       uint32_t& o0, uint32_t& o1)
{
    uint32_t k2 = k0 ^ k1 ^ 0x1BD11BDAu;
    x0 += k0; x1 += k1;
#define TFR(R) { x0 += x1; x1 = __funnelshift_l(x1,x1,R); x1 ^= x0; }
    TFR(13) TFR(15) TFR(26) TFR(6)
    x0 += k1; x1 += k2 + 1u;
    TFR(17) TFR(29) TFR(16) TFR(24)
    x0 += k2; x1 += k0 + 2u;
    TFR(13) TFR(15) TFR(26) TFR(6)
    x0 += k0; x1 += k1 + 3u;
    TFR(17) TFR(29) TFR(16) TFR(24)
    x0 += k1; x1 += k2 + 4u;
    TFR(13) TFR(15) TFR(26) TFR(6)
    x0 += k2; x1 += k0 + 5u;
#undef TFR
    o0 = x0; o1 = x1;
}
__device__ __forceinline__ uint32_t rbits32(uint32_t k0, uint32_t k1, uint32_t i)
{
    uint32_t o0, o1;
    tf2x32(k0, k1, 0u, i, o0, o1);
    return o0 ^ o1;
}
__global__ __launch_bounds__(256) void sample_kernel(
    const float* __restrict__ logits, float* __restrict__ out,
    uint32_t ck0, uint32_t ck1, uint32_t uk0, uint32_t uk1)
{
    __shared__ float sW[NRES];   // exp(-logit)
    int bv = blockIdx.x, t = threadIdx.x;
    if (t < NRES) sW[t] = expf(-logits[(size_t)bv*NRES + t]);
    __syncthreads();
    int warp = t>>5, lane = t&31;
#pragma unroll 1
    for (int it=0; it<16; it++) {
        int s = warp*16 + it;
        uint32_t p = (uint32_t)bv*128u + (uint32_t)s;
        float best = 3.4e38f; int bi = 0;
#pragma unroll
        for (int rr=0; rr<4; rr++) {
            int r = lane + 32*rr;
            uint32_t bits = rbits32(ck0, ck1, p*128u + (uint32_t)r);
            float u = __uint_as_float((bits >> 9) | 0x3f800000u) - 1.0f;
            u += 1.17549435e-38f;
            float v = (-__logf(u)) * sW[r];   // fast log (MUFU): ~3.5e-7 rel err
            if (v < best) { best = v; bi = r; }
        }
#pragma unroll
        for (int o=16;o;o>>=1) {
            float w = __shfl_down_sync(0xffffffffu,best,o);
            int   j = __shfl_down_sync(0xffffffffu,bi,o);
            if (w < best || (w == best && j < bi)) { best = w; bi = j; }
        }
        if (lane == 0) {
            float u = __uint_as_float((rbits32(uk0, uk1, p) >> 9) | 0x3f800000u) - 1.0f;
            out[p] = ((float)bi + u) * (1.0f/128.0f);
        }
    }
}

// ===== host =====
static inline uint32_t rotl32(uint32_t x,int r){ return (x<<r)|(x>>(32-r)); }
static void tf_host(uint32_t k0,uint32_t k1,uint32_t x0,uint32_t x1,uint32_t&o0,uint32_t&o1)
{
    uint32_t k2 = k0^k1^0x1BD11BDAu;
    x0+=k0; x1+=k1;
#define TFRH(R){ x0+=x1; x1=rotl32(x1,R); x1^=x0; }
    TFRH(13)TFRH(15)TFRH(26)TFRH(6)
    x0+=k1; x1+=k2+1u;
    TFRH(17)TFRH(29)TFRH(16)TFRH(24)
    x0+=k2; x1+=k0+2u;
    TFRH(13)TFRH(15)TFRH(26)TFRH(6)
    x0+=k0; x1+=k1+3u;
    TFRH(17)TFRH(29)TFRH(16)TFRH(24)
    x0+=k1; x1+=k2+4u;
    TFRH(13)TFRH(15)TFRH(26)TFRH(6)
    x0+=k2; x1+=k0+5u;
#undef TFRH
    o0=x0; o1=x1;
}

extern "C" void kernel_launch(void* const* d_in, const int* in_sizes, int n_in,
                              void* d_out, int out_size)
{
    (void)in_sizes; (void)n_in; (void)out_size;
    const float* flow=(const float*)d_in[0];
    const float* Wsh =(const float*)d_in[1];
    const float* bsh =(const float*)d_in[2];
    const float* Wk  =(const float*)d_in[3];
    const float* bk  =(const float*)d_in[4];
    const float* Wv  =(const float*)d_in[5];
    const float* bvv =(const float*)d_in[6];
    const float* l1g =(const float*)d_in[7];
    const float* l1b =(const float*)d_in[8];
    const float* l2g =(const float*)d_in[9];
    const float* l2b =(const float*)d_in[10];
    const float* W1  =(const float*)d_in[11];
    const float* b1  =(const float*)d_in[12];
    const float* W2  =(const float*)d_in[13];
    const float* b2  =(const float*)d_in[14];
    const float* W3  =(const float*)d_in[15];
    const float* b3  =(const float*)d_in[16];
    const float* Wd  =(const float*)d_in[17];
    const float* bd  =(const float*)d_in[18];
    float* out = (float*)d_out;

    float *att,*sc,*ctx,*lg;
    __nv_bfloat16 *qt0,*qt1,*qt2,*am0,*am1,*am2,*fs0,*fs1,*fs2;
    __nv_bfloat16 *kt0,*kt1,*kt2,*vt0,*vt1,*vt2,*ps0,*ps1,*ps2,*bs0,*bs1,*bs2;
    cudaGetSymbolAddress((void**)&att, g_att);
    cudaGetSymbolAddress((void**)&sc,  g_scores);
    cudaGetSymbolAddress((void**)&ctx, g_ctx);
    cudaGetSymbolAddress((void**)&lg,  g_logit);
    cudaGetSymbolAddress((void**)&qt0, g_qt0); cudaGetSymbolAddress((void**)&qt1, g_qt1);
    cudaGetSymbolAddress((void**)&qt2, g_qt2);
    cudaGetSymbolAddress((void**)&am0, g_am0); cudaGetSymbolAddress((void**)&am1, g_am1);
    cudaGetSymbolAddress((void**)&am2, g_am2);
    cudaGetSymbolAddress((void**)&fs0, g_fs0); cudaGetSymbolAddress((void**)&fs1, g_fs1);
    cudaGetSymbolAddress((void**)&fs2, g_fs2);
    cudaGetSymbolAddress((void**)&kt0, g_kt0); cudaGetSymbolAddress((void**)&kt1, g_kt1);
    cudaGetSymbolAddress((void**)&kt2, g_kt2);
    cudaGetSymbolAddress((void**)&vt0, g_vt0); cudaGetSymbolAddress((void**)&vt1, g_vt1);
    cudaGetSymbolAddress((void**)&vt2, g_vt2);
    cudaGetSymbolAddress((void**)&ps0, g_ps0); cudaGetSymbolAddress((void**)&ps1, g_ps1);
    cudaGetSymbolAddress((void**)&ps2, g_ps2);
    cudaGetSymbolAddress((void**)&bs0, g_bs0); cudaGetSymbolAddress((void**)&bs1, g_bs1);
    cudaGetSymbolAddress((void**)&bs2, g_bs2);

    static int smem_set = 0;
    if (!smem_set) {
        cudaFuncSetAttribute(mma_gemm,   cudaFuncAttributeMaxDynamicSharedMemorySize, MG_SMEM);
        cudaFuncSetAttribute(mma_scores, cudaFuncAttributeMaxDynamicSharedMemorySize, SC_SMEM);
        cudaFuncSetAttribute(mma_ctx,    cudaFuncAttributeMaxDynamicSharedMemorySize, CT_SMEM);
        smem_set = 1;
    }

    uint32_t k1a,k1b,k2a,k2b;
    tf_host(0u,1u,0u,0u,k1a,k1b);
    tf_host(0u,1u,0u,1u,k2a,k2b);

    auto tcg = [&](const __nv_bfloat16* a0,const __nv_bfloat16* a1,const __nv_bfloat16* a2,
                   long long boff, float* C, const float* bias,
                   __nv_bfloat16* o0, __nv_bfloat16* o1, __nv_bfloat16* o2,
                   int K, int N, int relu) {
        dim3 grid(N/128, MTOK/128);
        mma_gemm<<<grid,256,MG_SMEM>>>(a0,a1,a2, bs0+boff,bs1+boff,bs2+boff,
                                       C,bias,o0,o1,o2,K,N,relu);
    };
    auto wsplit = [&](const float* w, long long off, int R, int C, int batch) {
        dim3 g(C/32, R/32, batch);
        splitT_kernel<<<g,256>>>(w, bs0+off, bs1+off, bs2+off, R, C);
    };

    // weight splits (coalesced transpose)
    wsplit(Wsh, OFF_SH, ND, NHD, 1);
    wsplit(Wk,  OFF_K,  ND, NDH, NL*NH);   // per (l,h): [256,64] -> [64,256]
    wsplit(Wv,  OFF_V,  ND, NDH, NL*NH);
    for (int l=0;l<NL;l++) {
        wsplit(W1+(long long)l*NHD*NMLP,  OFF_W1(l), NHD,  NMLP, 1);
        wsplit(W2+(long long)l*NMLP*NMLP, OFF_W2(l), NMLP, NMLP, 1);
        wsplit(W3+(long long)l*NMLP*NHD,  OFF_W3(l), NMLP, NHD,  1);
    }
    wsplit(Wd, OFF_WD, NHD, NRES, 1);

    // input projections
    split3_kernel<<<(MTOK*ND+255)/256,256>>>(flow, am0,am1,am2, MTOK*ND);
    tcg(am0,am1,am2, OFF_SH, att, bsh, qt0,qt1,qt2, ND, NHD, 0);
    tcg(am0,am1,am2, OFF_K,  nullptr, bk,  kt0,kt1,kt2, ND, KVN, 0);
    tcg(am0,am1,am2, OFF_V,  nullptr, bvv, vt0,vt1,vt2, ND, KVN, 0);

    const int NR = NB*NH*NV;
    for (int l=0; l<NL; l++) {
        {
            dim3 g(4,4,NB*NH);
            mma_scores<<<g,256,SC_SMEM>>>(qt0,qt1,qt2, kt0,kt1,kt2, sc, l);
        }
        softmax512_split<<<(NR*32+255)/256,256>>>(sc, ps0,ps1,ps2, NR);
        {
            dim3 g(1,4,NB*NH);
            mma_ctx<<<g,256,CT_SMEM>>>(ps0,ps1,ps2, vt0,vt1,vt2, ctx, l);
        }
        add_ln_kernel<<<(MTOK*32+255)/256,256>>>(att, ctx, l1g+l*NHD, l1b+l*NHD, MTOK,
                                                 am0,am1,am2);
        tcg(am0,am1,am2, OFF_W1(l), nullptr, b1+(long long)l*NMLP, fs0,fs1,fs2, NHD, NMLP, 1);
        tcg(fs0,fs1,fs2, OFF_W2(l), nullptr, b2+(long long)l*NMLP, am0,am1,am2, NMLP, NMLP, 1);
        tcg(am0,am1,am2, OFF_W3(l), ctx, b3+(long long)l*NHD, 0,0,0, NMLP, NHD, 0);
        add_ln_kernel<<<(MTOK*32+255)/256,256>>>(att, ctx, l2g+l*NHD, l2b+l*NHD, MTOK,
                                                 qt0,qt1,qt2);
    }
    tcg(qt0,qt1,qt2, OFF_WD, lg, bd, 0,0,0, NHD, NRES, 0);
    sample_kernel<<<MTOK,256>>>(lg, out, k1a, k1b, k2a, k2b);
}

// round 12
// speedup vs baseline: 1.5055x; 1.5055x over previous
#include <cuda_runtime.h>
#include <cuda_bf16.h>
#include <cstdint>

#define NB 32
#define NV 512
#define ND 256
#define NL 4
#define NH 8
#define NDH 64
#define NHD 512
#define NMLP 1024
#define NRES 128
#define MTOK (NB*NV)
#define KVN (NL*NH*NDH)

__device__ float g_att[MTOK*NHD];
__device__ float g_scores[NB*NH*NV*NV];
__device__ float g_ctx[MTOK*NHD];
__device__ float g_logit[MTOK*NRES];
__device__ __nv_bfloat16 g_qt0[MTOK*NHD], g_qt1[MTOK*NHD], g_qt2[MTOK*NHD];
__device__ __nv_bfloat16 g_am0[MTOK*NMLP], g_am1[MTOK*NMLP], g_am2[MTOK*NMLP];
__device__ __nv_bfloat16 g_fs0[MTOK*NMLP], g_fs1[MTOK*NMLP], g_fs2[MTOK*NMLP];
__device__ __nv_bfloat16 g_kt0[MTOK*KVN], g_kt1[MTOK*KVN], g_kt2[MTOK*KVN];
__device__ __nv_bfloat16 g_vt0[MTOK*KVN], g_vt1[MTOK*KVN], g_vt2[MTOK*KVN];
__device__ __nv_bfloat16 g_ps0[NB*NH*NV*NV], g_ps1[NB*NH*NV*NV], g_ps2[NB*NH*NV*NV];
#define BS_TOT 9633792
__device__ __nv_bfloat16 g_bs0[BS_TOT], g_bs1[BS_TOT], g_bs2[BS_TOT];
#define OFF_SH 0
#define OFF_K  131072
#define OFF_V  655360
#define OFF_W1(l) (1179648 + (l)*2097152)
#define OFF_W2(l) (OFF_W1(l) + 524288)
#define OFF_W3(l) (OFF_W2(l) + 1048576)
#define OFF_WD 9568256

__device__ __forceinline__ void split3(float v, __nv_bfloat16& a, __nv_bfloat16& b, __nv_bfloat16& c)
{
    __nv_bfloat16 h0 = __float2bfloat16(v);
    float r1 = v - __bfloat162float(h0);
    __nv_bfloat16 h1 = __float2bfloat16(r1);
    float r2 = r1 - __bfloat162float(h1);
    a = h0; b = h1; c = __float2bfloat16(r2);
}
__global__ void split3_kernel(const float* __restrict__ x, __nv_bfloat16* __restrict__ o0,
    __nv_bfloat16* __restrict__ o1, __nv_bfloat16* __restrict__ o2, int n)
{
    int i = blockIdx.x*256 + threadIdx.x;
    if (i >= n) return;
    split3(x[i], o0[i], o1[i], o2[i]);
}
// Tiled transpose-split: per batch z, in = w[z] row-major [R,C]; out[z][c*R + r].
__global__ __launch_bounds__(256) void splitT_kernel(
    const float* __restrict__ w, __nv_bfloat16* __restrict__ o0,
    __nv_bfloat16* __restrict__ o1, __nv_bfloat16* __restrict__ o2, int R, int C)
{
    __shared__ float tile[32][33];
    int z = blockIdx.z;
    const float* wz = w + (size_t)z * R * C;
    size_t ob = (size_t)z * R * C;
    int c0 = blockIdx.x * 32, r0 = blockIdx.y * 32;
    int tx = threadIdx.x & 31, ty = threadIdx.x >> 5;
#pragma unroll
    for (int j = 0; j < 4; j++) {
        int r = ty * 4 + j;
        tile[r][tx] = wz[(size_t)(r0 + r) * C + c0 + tx];
    }
    __syncthreads();
#pragma unroll
    for (int j = 0; j < 4; j++) {
        int rr = ty * 4 + j;
        size_t g = ob + (size_t)(c0 + rr) * R + r0 + tx;
        split3(tile[tx][rr], o0[g], o1[g], o2[g]);
    }
}

// ===== common MMA helpers =====
__device__ __forceinline__ uint32_t s2u(const void* p) {
    uint32_t a;
    asm("{.reg .u64 t; cvta.to.shared.u64 t, %1; cvt.u32.u64 %0, t;}" : "=r"(a) : "l"(p));
    return a;
}
__device__ __forceinline__ void ldsm4(uint32_t* r, uint32_t addr) {
    asm volatile("ldmatrix.sync.aligned.m8n8.x4.shared.b16 {%0,%1,%2,%3},[%4];"
        : "=r"(r[0]), "=r"(r[1]), "=r"(r[2]), "=r"(r[3]) : "r"(addr));
}
__device__ __forceinline__ void ldsm4t(uint32_t* r, uint32_t addr) {
    asm volatile("ldmatrix.sync.aligned.m8n8.x4.trans.shared.b16 {%0,%1,%2,%3},[%4];"
        : "=r"(r[0]), "=r"(r[1]), "=r"(r[2]), "=r"(r[3]) : "r"(addr));
}
__device__ __forceinline__ void mma16816(float* d, const uint32_t* a, const uint32_t* b) {
    asm volatile("mma.sync.aligned.m16n8k16.row.col.f32.bf16.bf16.f32 "
        "{%0,%1,%2,%3},{%4,%5,%6,%7},{%8,%9},{%0,%1,%2,%3};"
        : "+f"(d[0]), "+f"(d[1]), "+f"(d[2]), "+f"(d[3])
        : "r"(a[0]), "r"(a[1]), "r"(a[2]), "r"(a[3]), "r"(b[0]), "r"(b[1]));
}
__device__ __forceinline__ uint32_t swq(int r, int q) { return (uint32_t)(q ^ ((r + (r >> 2)) & 3)); }

// ===== dense mma_gemm =====
#define MG_STAGE 49152
#define MG_SMEM  (2*MG_STAGE)
__global__ __launch_bounds__(256) void mma_gemm(
    const __nv_bfloat16* __restrict__ A0, const __nv_bfloat16* __restrict__ A1,
    const __nv_bfloat16* __restrict__ A2, const __nv_bfloat16* __restrict__ B0,
    const __nv_bfloat16* __restrict__ B1, const __nv_bfloat16* __restrict__ B2,
    float* __restrict__ C, const float* __restrict__ bias,
    __nv_bfloat16* __restrict__ o0, __nv_bfloat16* __restrict__ o1,
    __nv_bfloat16* __restrict__ o2, int K, int N, int relu)
{
    extern __shared__ __align__(128) char smem[];
    uint32_t sbase = s2u(smem);
    int tid = threadIdx.x, lane = tid & 31, wid = tid >> 5;
    int tm = blockIdx.y * 128, tn = blockIdx.x * 128;
    int wm = (wid >> 2) * 64, wn = (wid & 3) * 32;
    const __nv_bfloat16* Ap[3] = {A0, A1, A2};
    const __nv_bfloat16* Bp[3] = {B0, B1, B2};
    float acc[4][4][4];
#pragma unroll
    for (int a = 0; a < 4; a++)
#pragma unroll
        for (int b = 0; b < 4; b++)
#pragma unroll
            for (int c = 0; c < 4; c++) acc[a][b][c] = 0.f;
    auto load = [&](int c) {
        int kc = c * 32;
        uint32_t sb = sbase + (c & 1) * MG_STAGE;
#pragma unroll
        for (int i = 0; i < 12; i++) {
            int f = tid + i * 256;
            int comp = f >> 9, idx = f & 511;
            int r = idx >> 2, q = idx & 3;
            const __nv_bfloat16* src = (comp < 3)
                ? Ap[comp] + (size_t)(tm + r) * K + kc + q * 8
                : Bp[comp - 3] + (size_t)(tn + r) * K + kc + q * 8;
            uint32_t dst = sb + comp * 8192 + r * 64 + (swq(r, q) << 4);
            asm volatile("cp.async.cg.shared.global [%0],[%1],16;" :: "r"(dst), "l"(src));
        }
        asm volatile("cp.async.commit_group;" ::: "memory");
    };
    int nc = K >> 5;
    load(0);
    for (int c = 0; c < nc; c++) {
        if (c + 1 < nc) { load(c + 1); asm volatile("cp.async.wait_group 1;" ::: "memory"); }
        else asm volatile("cp.async.wait_group 0;" ::: "memory");
        __syncthreads();
        uint32_t sb = sbase + (c & 1) * MG_STAGE;
#pragma unroll
        for (int ks = 0; ks < 2; ks++) {
            uint32_t bf[3][8];
#pragma unroll
            for (int bc = 0; bc < 3; bc++)
#pragma unroll
                for (int h = 0; h < 2; h++) {
                    int mat = lane >> 3;
                    int n = wn + h * 16 + (mat >> 1) * 8 + (lane & 7);
                    int kq = ks * 2 + (mat & 1);
                    ldsm4(&bf[bc][h * 4], sb + (3 + bc) * 8192 + n * 64 + (swq(n, kq) << 4));
                }
#pragma unroll
            for (int ac = 0; ac < 3; ac++) {
                uint32_t af[16];
#pragma unroll
                for (int mt = 0; mt < 4; mt++) {
                    int mat = lane >> 3;
                    int row = wm + mt * 16 + (mat & 1) * 8 + (lane & 7);
                    int kq = ks * 2 + (mat >> 1);
                    ldsm4(&af[mt * 4], sb + ac * 8192 + row * 64 + (swq(row, kq) << 4));
                }
#pragma unroll
                for (int bc = 0; bc < 3 - ac; bc++)
#pragma unroll
                    for (int mt = 0; mt < 4; mt++)
#pragma unroll
                        for (int nt = 0; nt < 4; nt++)
                            mma16816(acc[mt][nt], &af[mt * 4],
                                     &bf[bc][(nt >> 1) * 4 + (nt & 1) * 2]);
            }
        }
        __syncthreads();
    }
    int r0 = lane >> 2, c0 = (lane & 3) * 2;
    float* Cs = (float*)smem;
#pragma unroll
    for (int mt = 0; mt < 4; mt++)
#pragma unroll
        for (int i = 0; i < 2; i++) {
            int rl = wm + mt * 16 + r0 + i * 8;
            int row = tm + rl;
#pragma unroll
            for (int nt = 0; nt < 4; nt++) {
                int cl = wn + nt * 8 + c0;
                int col = tn + cl;
                float v0 = acc[mt][nt][i * 2 + 0] + bias[col];
                float v1 = acc[mt][nt][i * 2 + 1] + bias[col + 1];
                if (relu) { v0 = fmaxf(v0, 0.f); v1 = fmaxf(v1, 0.f); }
                if (C) *(float2*)&C[(size_t)row * N + col] = make_float2(v0, v1);
                if (o0) { Cs[rl * 132 + cl] = v0; Cs[rl * 132 + cl + 1] = v1; }
            }
        }
    if (o0) {
        __syncthreads();
#pragma unroll 1
        for (int it = 0; it < 64; it++) {
            int idx = it * 256 + tid;
            int r = idx >> 7, cl = idx & 127;
            size_t g = (size_t)(tm + r) * N + tn + cl;
            split3(Cs[r * 132 + cl], o0[g], o1[g], o2[g]);
        }
    }
}

// ===== batched scores MMA =====
#define SC_SMEM (6*16384)
__global__ __launch_bounds__(256) void mma_scores(
    const __nv_bfloat16* __restrict__ Q0, const __nv_bfloat16* __restrict__ Q1,
    const __nv_bfloat16* __restrict__ Q2, const __nv_bfloat16* __restrict__ K0,
    const __nv_bfloat16* __restrict__ K1, const __nv_bfloat16* __restrict__ K2,
    float* __restrict__ sc, int l)
{
    extern __shared__ __align__(128) char smem[];
    uint32_t sbase = s2u(smem);
    int tid = threadIdx.x, lane = tid & 31, wid = tid >> 5;
    int z = blockIdx.z, b = z >> 3, h = z & 7;
    int tm = blockIdx.y * 128, tn = blockIdx.x * 128;
    int wm = (wid >> 2) * 64, wn = (wid & 3) * 32;
    const __nv_bfloat16* Qp[3] = {Q0, Q1, Q2};
    const __nv_bfloat16* Kp[3] = {K0, K1, K2};
    size_t qoff = (size_t)(b * 512 + tm) * NHD + h * 64;
    size_t koff = (size_t)(b * 512 + tn) * KVN + l * 512 + h * 64;
#pragma unroll
    for (int i = 0; i < 24; i++) {
        int f = tid + i * 256;
        int comp = f >> 10, idx = f & 1023;
        int r = idx >> 3, q = idx & 7;
        const __nv_bfloat16* src = (comp < 3)
            ? Qp[comp] + qoff + (size_t)r * NHD + q * 8
            : Kp[comp - 3] + koff + (size_t)r * KVN + q * 8;
        uint32_t dst = sbase + comp * 16384 + r * 128 + ((uint32_t)(q ^ (r & 7)) << 4);
        asm volatile("cp.async.cg.shared.global [%0],[%1],16;" :: "r"(dst), "l"(src));
    }
    asm volatile("cp.async.commit_group;" ::: "memory");
    asm volatile("cp.async.wait_group 0;" ::: "memory");
    __syncthreads();
    float acc[4][4][4];
#pragma unroll
    for (int a = 0; a < 4; a++)
#pragma unroll
        for (int bb = 0; bb < 4; bb++)
#pragma unroll
            for (int c = 0; c < 4; c++) acc[a][bb][c] = 0.f;
#pragma unroll
    for (int ks = 0; ks < 4; ks++) {
        uint32_t bf[3][8];
#pragma unroll
        for (int bc = 0; bc < 3; bc++)
#pragma unroll
            for (int hh = 0; hh < 2; hh++) {
                int mat = lane >> 3;
                int n = wn + hh * 16 + (mat >> 1) * 8 + (lane & 7);
                int kq = ks * 2 + (mat & 1);
                ldsm4(&bf[bc][hh * 4], sbase + (3 + bc) * 16384 + n * 128 + ((uint32_t)(kq ^ (n & 7)) << 4));
            }
#pragma unroll
        for (int ac = 0; ac < 3; ac++) {
            uint32_t af[16];
#pragma unroll
            for (int mt = 0; mt < 4; mt++) {
                int mat = lane >> 3;
                int row = wm + mt * 16 + (mat & 1) * 8 + (lane & 7);
                int kq = ks * 2 + (mat >> 1);
                ldsm4(&af[mt * 4], sbase + ac * 16384 + row * 128 + ((uint32_t)(kq ^ (row & 7)) << 4));
            }
#pragma unroll
            for (int bc = 0; bc < 3 - ac; bc++)
#pragma unroll
                for (int mt = 0; mt < 4; mt++)
#pragma unroll
                    for (int nt = 0; nt < 4; nt++)
                        mma16816(acc[mt][nt], &af[mt * 4], &bf[bc][(nt >> 1) * 4 + (nt & 1) * 2]);
        }
    }
    int r0 = lane >> 2, c0 = (lane & 3) * 2;
    float* scz = sc + (size_t)z * NV * NV;
#pragma unroll
    for (int mt = 0; mt < 4; mt++)
#pragma unroll
        for (int i = 0; i < 2; i++) {
            int row = tm + wm + mt * 16 + r0 + i * 8;
#pragma unroll
            for (int nt = 0; nt < 4; nt++) {
                int col = tn + wn + nt * 8 + c0;
                *(float2*)&scz[(size_t)row * NV + col] = make_float2(
                    acc[mt][nt][i * 2 + 0] * 0.125f, acc[mt][nt][i * 2 + 1] * 0.125f);
            }
        }
}

// ===== batched ctx MMA =====
#define CT_STAGE 73728
#define CT_SMEM (2*CT_STAGE)
__global__ __launch_bounds__(256) void mma_ctx(
    const __nv_bfloat16* __restrict__ P0, const __nv_bfloat16* __restrict__ P1,
    const __nv_bfloat16* __restrict__ P2, const __nv_bfloat16* __restrict__ V0,
    const __nv_bfloat16* __restrict__ V1, const __nv_bfloat16* __restrict__ V2,
    float* __restrict__ C, int l)
{
    extern __shared__ __align__(128) char smem[];
    uint32_t sbase = s2u(smem);
    int tid = threadIdx.x, lane = tid & 31, wid = tid >> 5;
    int z = blockIdx.z, b = z >> 3, h = z & 7;
    int tm = blockIdx.y * 128;
    int wm = (wid >> 1) * 32, wn = (wid & 1) * 32;
    const __nv_bfloat16* Pp[3] = {P0, P1, P2};
    const __nv_bfloat16* Vp[3] = {V0, V1, V2};
    size_t poff = ((size_t)z * 512 + tm) * 512;
    size_t voff = (size_t)(b * 512) * KVN + l * 512 + h * 64;
    float acc[2][4][4];
#pragma unroll
    for (int a = 0; a < 2; a++)
#pragma unroll
        for (int bb = 0; bb < 4; bb++)
#pragma unroll
            for (int c = 0; c < 4; c++) acc[a][bb][c] = 0.f;
    auto load = [&](int c) {
        int kc = c * 64;
        uint32_t sb = sbase + (c & 1) * CT_STAGE;
#pragma unroll
        for (int i = 0; i < 18; i++) {
            int f = tid + i * 256;
            if (f < 3072) {
                int comp = f >> 10, idx = f & 1023;
                int r = idx >> 3, q = idx & 7;
                const __nv_bfloat16* src = Pp[comp] + poff + (size_t)r * 512 + kc + q * 8;
                uint32_t dst = sb + comp * 16384 + r * 128 + ((uint32_t)(q ^ (r & 7)) << 4);
                asm volatile("cp.async.cg.shared.global [%0],[%1],16;" :: "r"(dst), "l"(src));
            } else {
                int g = f - 3072;
                int comp = g >> 9, idx = g & 511;
                int kr = idx >> 3, q = idx & 7;
                const __nv_bfloat16* src = Vp[comp] + voff + (size_t)(kc + kr) * KVN + q * 8;
                uint32_t dst = sb + 49152 + comp * 8192 + kr * 128 + ((uint32_t)(q ^ (kr & 7)) << 4);
                asm volatile("cp.async.cg.shared.global [%0],[%1],16;" :: "r"(dst), "l"(src));
            }
        }
        asm volatile("cp.async.commit_group;" ::: "memory");
    };
    load(0);
    for (int c = 0; c < 8; c++) {
        if (c + 1 < 8) { load(c + 1); asm volatile("cp.async.wait_group 1;" ::: "memory"); }
        else asm volatile("cp.async.wait_group 0;" ::: "memory");
        __syncthreads();
        uint32_t sb = sbase + (c & 1) * CT_STAGE;
#pragma unroll
        for (int ks = 0; ks < 4; ks++) {
            uint32_t bf[3][8];
#pragma unroll
            for (int bc = 0; bc < 3; bc++)
#pragma unroll
                for (int j = 0; j < 2; j++) {
                    int krow = ks * 16 + (lane & 15);
                    int qn = ((wn + j * 16) >> 3) + (lane >> 4);
                    ldsm4t(&bf[bc][j * 4],
                           sb + 49152 + bc * 8192 + krow * 128 + ((uint32_t)(qn ^ (krow & 7)) << 4));
                }
#pragma unroll
            for (int ac = 0; ac < 3; ac++) {
                uint32_t af[8];
#pragma unroll
                for (int mt = 0; mt < 2; mt++) {
                    int mat = lane >> 3;
                    int row = wm + mt * 16 + (mat & 1) * 8 + (lane & 7);
                    int kq = ks * 2 + (mat >> 1);
                    ldsm4(&af[mt * 4], sb + ac * 16384 + row * 128 + ((uint32_t)(kq ^ (row & 7)) << 4));
                }
#pragma unroll
                for (int bc = 0; bc < 3 - ac; bc++)
#pragma unroll
                    for (int mt = 0; mt < 2; mt++)
#pragma unroll
                        for (int nt = 0; nt < 4; nt++)
                            mma16816(acc[mt][nt], &af[mt * 4], &bf[bc][(nt >> 1) * 4 + (nt & 1) * 2]);
            }
        }
        __syncthreads();
    }
    int r0 = lane >> 2, c0 = (lane & 3) * 2;
#pragma unroll
    for (int mt = 0; mt < 2; mt++)
#pragma unroll
        for (int i = 0; i < 2; i++) {
            int row = b * 512 + tm + wm + mt * 16 + r0 + i * 8;
#pragma unroll
            for (int nt = 0; nt < 4; nt++) {
                int col = h * 64 + wn + nt * 8 + c0;
                *(float2*)&C[(size_t)row * NHD + col] =
                    make_float2(acc[mt][nt][i * 2 + 0], acc[mt][nt][i * 2 + 1]);
            }
        }
}

// ===== softmax (emits bf16 splits of probs) =====
__global__ __launch_bounds__(256) void softmax512_split(
    const float* __restrict__ x, __nv_bfloat16* __restrict__ p0,
    __nv_bfloat16* __restrict__ p1, __nv_bfloat16* __restrict__ p2, int nrows)
{
    int gw = (blockIdx.x*256 + threadIdx.x) >> 5;
    if (gw >= nrows) return;
    int lane = threadIdx.x & 31;
    const float* row = x + (size_t)gw*512;
    float v[16], m = -3.4e38f;
#pragma unroll
    for (int i=0;i<16;i++){ v[i]=row[lane+32*i]; m=fmaxf(m,v[i]); }
#pragma unroll
    for (int o=16;o;o>>=1) m = fmaxf(m, __shfl_xor_sync(0xffffffffu,m,o));
    float s = 0.f;
#pragma unroll
    for (int i=0;i<16;i++){ v[i]=expf(v[i]-m); s+=v[i]; }
#pragma unroll
    for (int o=16;o;o>>=1) s += __shfl_xor_sync(0xffffffffu,s,o);
    float inv = 1.f/s;
#pragma unroll
    for (int i=0;i<16;i++) {
        size_t idx = (size_t)gw*512 + lane + 32*i;
        split3(v[i]*inv, p0[idx], p1[idx], p2[idx]);
    }
}

// ===== add + layernorm, emits bf16 splits =====
__global__ __launch_bounds__(256) void add_ln_kernel(
    float* __restrict__ att, const float* __restrict__ d,
    const float* __restrict__ g, const float* __restrict__ b, int nrows,
    __nv_bfloat16* __restrict__ o0, __nv_bfloat16* __restrict__ o1,
    __nv_bfloat16* __restrict__ o2)
{
    int gw = (blockIdx.x*256 + threadIdx.x) >> 5;
    if (gw >= nrows) return;
    int lane = threadIdx.x & 31;
    float* row = att + (size_t)gw*512;
    const float* dr = d + (size_t)gw*512;
    float v[16], s = 0.f;
#pragma unroll
    for (int i=0;i<16;i++){ v[i]=row[lane+32*i]+dr[lane+32*i]; s+=v[i]; }
#pragma unroll
    for (int o=16;o;o>>=1) s += __shfl_xor_sync(0xffffffffu,s,o);
    float mean = s*(1.f/512.f), q = 0.f;
#pragma unroll
    for (int i=0;i<16;i++){ float e=v[i]-mean; q+=e*e; }
#pragma unroll
    for (int o=16;o;o>>=1) q += __shfl_xor_sync(0xffffffffu,q,o);
    float inv = rsqrtf(q*(1.f/512.f) + 1e-5f);
#pragma unroll
    for (int i=0;i<16;i++){
        int c = lane+32*i;
        float val = (v[i]-mean)*inv*g[c]+b[c];
        row[c] = val;
        size_t idx = (size_t)gw*512 + c;
        split3(val, o0[idx], o1[idx], o2[idx]);
    }
}

// ===== sampling: argmax(gumbel+L) == argmin((-log u) * exp(-L)), accurate logf =====
__device__ __forceinline__ void tf2x32(uint32_t k0, uint32_t k1, uint32_t x0, uint32_t x1,
                                       uint32_t& o0, uint32_t& o1)
{
    uint32_t k2 = k0 ^ k1 ^ 0x1BD11BDAu;
    x0 += k0; x1 += k1;
#define TFR(R) { x0 += x1; x1 = __funnelshift_l(x1,x1,R); x1 ^= x0; }
    TFR(13) TFR(15) TFR(26) TFR(6)
    x0 += k1; x1 += k2 + 1u;
    TFR(17) TFR(29) TFR(16) TFR(24)
    x0 += k2; x1 += k0 + 2u;
    TFR(13) TFR(15) TFR(26) TFR(6)
    x0 += k0; x1 += k1 + 3u;
    TFR(17) TFR(29) TFR(16) TFR(24)
    x0 += k1; x1 += k2 + 4u;
    TFR(13) TFR(15) TFR(26) TFR(6)
    x0 += k2; x1 += k0 + 5u;
#undef TFR
    o0 = x0; o1 = x1;
}
__device__ __forceinline__ uint32_t rbits32(uint32_t k0, uint32_t k1, uint32_t i)
{
    uint32_t o0, o1;
    tf2x32(k0, k1, 0u, i, o0, o1);
    return o0 ^ o1;
}
__global__ __launch_bounds__(256) void sample_kernel(
    const float* __restrict__ logits, float* __restrict__ out,
    uint32_t ck0, uint32_t ck1, uint32_t uk0, uint32_t uk1)
{
    __shared__ float sW[NRES];   // exp(-logit)
    int bv = blockIdx.x, t = threadIdx.x;
    if (t < NRES) sW[t] = expf(-logits[(size_t)bv*NRES + t]);
    __syncthreads();
    int warp = t>>5, lane = t&31;
#pragma unroll 1
    for (int it=0; it<16; it++) {
        int s = warp*16 + it;
        uint32_t p = (uint32_t)bv*128u + (uint32_t)s;
        float best = 3.4e38f; int bi = 0;
#pragma unroll
        for (int rr=0; rr<4; rr++) {
            int r = lane + 32*rr;
            uint32_t bits = rbits32(ck0, ck1, p*128u + (uint32_t)r);
            float u = __uint_as_float((bits >> 9) | 0x3f800000u) - 1.0f;
            u += 1.17549435e-38f;
            float v = (-logf(u)) * sW[r];
            if (v < best) { best = v; bi = r; }
        }
#pragma unroll
        for (int o=16;o;o>>=1) {
            float w = __shfl_down_sync(0xffffffffu,best,o);
            int   j = __shfl_down_sync(0xffffffffu,bi,o);
            if (w < best || (w == best && j < bi)) { best = w; bi = j; }
        }
        if (lane == 0) {
            float u = __uint_as_float((rbits32(uk0, uk1, p) >> 9) | 0x3f800000u) - 1.0f;
            out[p] = ((float)bi + u) * (1.0f/128.0f);
        }
    }
}

// ===== host =====
static inline uint32_t rotl32(uint32_t x,int r){ return (x<<r)|(x>>(32-r)); }
static void tf_host(uint32_t k0,uint32_t k1,uint32_t x0,uint32_t x1,uint32_t&o0,uint32_t&o1)
{
    uint32_t k2 = k0^k1^0x1BD11BDAu;
    x0+=k0; x1+=k1;
#define TFRH(R){ x0+=x1; x1=rotl32(x1,R); x1^=x0; }
    TFRH(13)TFRH(15)TFRH(26)TFRH(6)
    x0+=k1; x1+=k2+1u;
    TFRH(17)TFRH(29)TFRH(16)TFRH(24)
    x0+=k2; x1+=k0+2u;
    TFRH(13)TFRH(15)TFRH(26)TFRH(6)
    x0+=k0; x1+=k1+3u;
    TFRH(17)TFRH(29)TFRH(16)TFRH(24)
    x0+=k1; x1+=k2+4u;
    TFRH(13)TFRH(15)TFRH(26)TFRH(6)
    x0+=k2; x1+=k0+5u;
#undef TFRH
    o0=x0; o1=x1;
}

extern "C" void kernel_launch(void* const* d_in, const int* in_sizes, int n_in,
                              void* d_out, int out_size)
{
    (void)in_sizes; (void)n_in; (void)out_size;
    const float* flow=(const float*)d_in[0];
    const float* Wsh =(const float*)d_in[1];
    const float* bsh =(const float*)d_in[2];
    const float* Wk  =(const float*)d_in[3];
    const float* bk  =(const float*)d_in[4];
    const float* Wv  =(const float*)d_in[5];
    const float* bvv =(const float*)d_in[6];
    const float* l1g =(const float*)d_in[7];
    const float* l1b =(const float*)d_in[8];
    const float* l2g =(const float*)d_in[9];
    const float* l2b =(const float*)d_in[10];
    const float* W1  =(const float*)d_in[11];
    const float* b1  =(const float*)d_in[12];
    const float* W2  =(const float*)d_in[13];
    const float* b2  =(const float*)d_in[14];
    const float* W3  =(const float*)d_in[15];
    const float* b3  =(const float*)d_in[16];
    const float* Wd  =(const float*)d_in[17];
    const float* bd  =(const float*)d_in[18];
    float* out = (float*)d_out;

    float *att,*sc,*ctx,*lg;
    __nv_bfloat16 *qt0,*qt1,*qt2,*am0,*am1,*am2,*fs0,*fs1,*fs2;
    __nv_bfloat16 *kt0,*kt1,*kt2,*vt0,*vt1,*vt2,*ps0,*ps1,*ps2,*bs0,*bs1,*bs2;
    cudaGetSymbolAddress((void**)&att, g_att);
    cudaGetSymbolAddress((void**)&sc,  g_scores);
    cudaGetSymbolAddress((void**)&ctx, g_ctx);
    cudaGetSymbolAddress((void**)&lg,  g_logit);
    cudaGetSymbolAddress((void**)&qt0, g_qt0); cudaGetSymbolAddress((void**)&qt1, g_qt1);
    cudaGetSymbolAddress((void**)&qt2, g_qt2);
    cudaGetSymbolAddress((void**)&am0, g_am0); cudaGetSymbolAddress((void**)&am1, g_am1);
    cudaGetSymbolAddress((void**)&am2, g_am2);
    cudaGetSymbolAddress((void**)&fs0, g_fs0); cudaGetSymbolAddress((void**)&fs1, g_fs1);
    cudaGetSymbolAddress((void**)&fs2, g_fs2);
    cudaGetSymbolAddress((void**)&kt0, g_kt0); cudaGetSymbolAddress((void**)&kt1, g_kt1);
    cudaGetSymbolAddress((void**)&kt2, g_kt2);
    cudaGetSymbolAddress((void**)&vt0, g_vt0); cudaGetSymbolAddress((void**)&vt1, g_vt1);
    cudaGetSymbolAddress((void**)&vt2, g_vt2);
    cudaGetSymbolAddress((void**)&ps0, g_ps0); cudaGetSymbolAddress((void**)&ps1, g_ps1);
    cudaGetSymbolAddress((void**)&ps2, g_ps2);
    cudaGetSymbolAddress((void**)&bs0, g_bs0); cudaGetSymbolAddress((void**)&bs1, g_bs1);
    cudaGetSymbolAddress((void**)&bs2, g_bs2);

    static int smem_set = 0;
    if (!smem_set) {
        cudaFuncSetAttribute(mma_gemm,   cudaFuncAttributeMaxDynamicSharedMemorySize, MG_SMEM);
        cudaFuncSetAttribute(mma_scores, cudaFuncAttributeMaxDynamicSharedMemorySize, SC_SMEM);
        cudaFuncSetAttribute(mma_ctx,    cudaFuncAttributeMaxDynamicSharedMemorySize, CT_SMEM);
        smem_set = 1;
    }

    uint32_t k1a,k1b,k2a,k2b;
    tf_host(0u,1u,0u,0u,k1a,k1b);
    tf_host(0u,1u,0u,1u,k2a,k2b);

    auto tcg = [&](const __nv_bfloat16* a0,const __nv_bfloat16* a1,const __nv_bfloat16* a2,
                   long long boff, float* C, const float* bias,
                   __nv_bfloat16* o0, __nv_bfloat16* o1, __nv_bfloat16* o2,
                   int K, int N, int relu) {
        dim3 grid(N/128, MTOK/128);
        mma_gemm<<<grid,256,MG_SMEM>>>(a0,a1,a2, bs0+boff,bs1+boff,bs2+boff,
                                       C,bias,o0,o1,o2,K,N,relu);
    };
    auto wsplit = [&](const float* w, long long off, int R, int C, int batch) {
        dim3 g(C/32, R/32, batch);
        splitT_kernel<<<g,256>>>(w, bs0+off, bs1+off, bs2+off, R, C);
    };

    // weight splits (coalesced transpose)
    wsplit(Wsh, OFF_SH, ND, NHD, 1);
    wsplit(Wk,  OFF_K,  ND, NDH, NL*NH);
    wsplit(Wv,  OFF_V,  ND, NDH, NL*NH);
    for (int l=0;l<NL;l++) {
        wsplit(W1+(long long)l*NHD*NMLP,  OFF_W1(l), NHD,  NMLP, 1);
        wsplit(W2+(long long)l*NMLP*NMLP, OFF_W2(l), NMLP, NMLP, 1);
        wsplit(W3+(long long)l*NMLP*NHD,  OFF_W3(l), NMLP, NHD,  1);
    }
    wsplit(Wd, OFF_WD, NHD, NRES, 1);

    // input projections
    split3_kernel<<<(MTOK*ND+255)/256,256>>>(flow, am0,am1,am2, MTOK*ND);
    tcg(am0,am1,am2, OFF_SH, att, bsh, qt0,qt1,qt2, ND, NHD, 0);
    tcg(am0,am1,am2, OFF_K,  nullptr, bk,  kt0,kt1,kt2, ND, KVN, 0);
    tcg(am0,am1,am2, OFF_V,  nullptr, bvv, vt0,vt1,vt2, ND, KVN, 0);

    const int NR = NB*NH*NV;
    for (int l=0; l<NL; l++) {
        {
            dim3 g(4,4,NB*NH);
            mma_scores<<<g,256,SC_SMEM>>>(qt0,qt1,qt2, kt0,kt1,kt2, sc, l);
        }
        softmax512_split<<<(NR*32+255)/256,256>>>(sc, ps0,ps1,ps2, NR);
        {
            dim3 g(1,4,NB*NH);
            mma_ctx<<<g,256,CT_SMEM>>>(ps0,ps1,ps2, vt0,vt1,vt2, ctx, l);
        }
        add_ln_kernel<<<(MTOK*32+255)/256,256>>>(att, ctx, l1g+l*NHD, l1b+l*NHD, MTOK,
                                                 am0,am1,am2);
        tcg(am0,am1,am2, OFF_W1(l), nullptr, b1+(long long)l*NMLP, fs0,fs1,fs2, NHD, NMLP, 1);
        tcg(fs0,fs1,fs2, OFF_W2(l), nullptr, b2+(long long)l*NMLP, am0,am1,am2, NMLP, NMLP, 1);
        tcg(am0,am1,am2, OFF_W3(l), ctx, b3+(long long)l*NHD, 0,0,0, NMLP, NHD, 0);
        add_ln_kernel<<<(MTOK*32+255)/256,256>>>(att, ctx, l2g+l*NHD, l2b+l*NHD, MTOK,
                                                 qt0,qt1,qt2);
    }
    tcg(qt0,qt1,qt2, OFF_WD, lg, bd, 0,0,0, NHD, NRES, 0);
    sample_kernel<<<MTOK,256>>>(lg, out, k1a, k1b, k2a, k2b);
}

// round 13
// speedup vs baseline: 2.1334x; 1.4170x over previous
#include <cuda_runtime.h>
#include <cuda_bf16.h>
#include <cuda_fp16.h>
#include <cstdint>

#define NB 32
#define NV 512
#define ND 256
#define NL 4
#define NH 8
#define NDH 64
#define NHD 512
#define NMLP 1024
#define NRES 128
#define MTOK (NB*NV)
#define KVN (NL*NH*NDH)

__device__ float g_att[MTOK*NHD];
__device__ float g_scores[NB*NH*NV*NV];
__device__ float g_ctx[MTOK*NHD];
__device__ float g_logit[MTOK*NRES];
__device__ __nv_bfloat16 g_qt0[MTOK*NHD], g_qt1[MTOK*NHD], g_qt2[MTOK*NHD];
__device__ __nv_bfloat16 g_kt0[MTOK*KVN], g_kt1[MTOK*KVN], g_kt2[MTOK*KVN];
__device__ __nv_bfloat16 g_vt0[MTOK*KVN], g_vt1[MTOK*KVN], g_vt2[MTOK*KVN];
__device__ __nv_bfloat16 g_ps0[NB*NH*NV*NV], g_ps1[NB*NH*NV*NV], g_ps2[NB*NH*NV*NV];
__device__ __nv_bfloat16 g_am0[MTOK*ND], g_am1[MTOK*ND], g_am2[MTOK*ND];   // flow splits
#define BS_TOT 9633792
__device__ __nv_bfloat16 g_bs0[BS_TOT], g_bs1[BS_TOT], g_bs2[BS_TOT];
#define OFF_SH 0
#define OFF_K  131072
#define OFF_V  655360
#define OFF_WD 9568256
// fp16 2-split buffers (MLP)
__device__ __half g_h0[MTOK*NMLP], g_h1[MTOK*NMLP];
__device__ __half g_i0[MTOK*NMLP], g_i1[MTOK*NMLP];
#define HW_TOT 8388608
__device__ __half g_hw0[HW_TOT], g_hw1[HW_TOT];
#define HOFF_W1(l) ((l)*2097152)
#define HOFF_W2(l) (HOFF_W1(l) + 524288)
#define HOFF_W3(l) (HOFF_W2(l) + 1048576)

__device__ __forceinline__ void split3(float v, __nv_bfloat16& a, __nv_bfloat16& b, __nv_bfloat16& c)
{
    __nv_bfloat16 h0 = __float2bfloat16(v);
    float r1 = v - __bfloat162float(h0);
    __nv_bfloat16 h1 = __float2bfloat16(r1);
    float r2 = r1 - __bfloat162float(h1);
    a = h0; b = h1; c = __float2bfloat16(r2);
}
__device__ __forceinline__ void split2h(float v, __half& a, __half& b)
{
    __half h0 = __float2half_rn(v);
    a = h0; b = __float2half_rn(v - __half2float(h0));
}
__global__ void split3_kernel(const float* __restrict__ x, __nv_bfloat16* __restrict__ o0,
    __nv_bfloat16* __restrict__ o1, __nv_bfloat16* __restrict__ o2, int n)
{
    int i = blockIdx.x*256 + threadIdx.x;
    if (i >= n) return;
    split3(x[i], o0[i], o1[i], o2[i]);
}
__global__ __launch_bounds__(256) void splitT_kernel(
    const float* __restrict__ w, __nv_bfloat16* __restrict__ o0,
    __nv_bfloat16* __restrict__ o1, __nv_bfloat16* __restrict__ o2, int R, int C)
{
    __shared__ float tile[32][33];
    int z = blockIdx.z;
    const float* wz = w + (size_t)z * R * C;
    size_t ob = (size_t)z * R * C;
    int c0 = blockIdx.x * 32, r0 = blockIdx.y * 32;
    int tx = threadIdx.x & 31, ty = threadIdx.x >> 5;
#pragma unroll
    for (int j = 0; j < 4; j++) {
        int r = ty * 4 + j;
        tile[r][tx] = wz[(size_t)(r0 + r) * C + c0 + tx];
    }
    __syncthreads();
#pragma unroll
    for (int j = 0; j < 4; j++) {
        int rr = ty * 4 + j;
        size_t g = ob + (size_t)(c0 + rr) * R + r0 + tx;
        split3(tile[tx][rr], o0[g], o1[g], o2[g]);
    }
}
__global__ __launch_bounds__(256) void splitT2h_kernel(
    const float* __restrict__ w, __half* __restrict__ o0, __half* __restrict__ o1,
    int R, int C)
{
    __shared__ float tile[32][33];
    const float* wz = w;
    int c0 = blockIdx.x * 32, r0 = blockIdx.y * 32;
    int tx = threadIdx.x & 31, ty = threadIdx.x >> 5;
#pragma unroll
    for (int j = 0; j < 4; j++) {
        int r = ty * 4 + j;
        tile[r][tx] = wz[(size_t)(r0 + r) * C + c0 + tx];
    }
    __syncthreads();
#pragma unroll
    for (int j = 0; j < 4; j++) {
        int rr = ty * 4 + j;
        size_t g = (size_t)(c0 + rr) * R + r0 + tx;
        split2h(tile[tx][rr], o0[g], o1[g]);
    }
}

// ===== common MMA helpers =====
__device__ __forceinline__ uint32_t s2u(const void* p) {
    uint32_t a;
    asm("{.reg .u64 t; cvta.to.shared.u64 t, %1; cvt.u32.u64 %0, t;}" : "=r"(a) : "l"(p));
    return a;
}
__device__ __forceinline__ void ldsm4(uint32_t* r, uint32_t addr) {
    asm volatile("ldmatrix.sync.aligned.m8n8.x4.shared.b16 {%0,%1,%2,%3},[%4];"
        : "=r"(r[0]), "=r"(r[1]), "=r"(r[2]), "=r"(r[3]) : "r"(addr));
}
__device__ __forceinline__ void ldsm4t(uint32_t* r, uint32_t addr) {
    asm volatile("ldmatrix.sync.aligned.m8n8.x4.trans.shared.b16 {%0,%1,%2,%3},[%4];"
        : "=r"(r[0]), "=r"(r[1]), "=r"(r[2]), "=r"(r[3]) : "r"(addr));
}
__device__ __forceinline__ void mma16816(float* d, const uint32_t* a, const uint32_t* b) {
    asm volatile("mma.sync.aligned.m16n8k16.row.col.f32.bf16.bf16.f32 "
        "{%0,%1,%2,%3},{%4,%5,%6,%7},{%8,%9},{%0,%1,%2,%3};"
        : "+f"(d[0]), "+f"(d[1]), "+f"(d[2]), "+f"(d[3])
        : "r"(a[0]), "r"(a[1]), "r"(a[2]), "r"(a[3]), "r"(b[0]), "r"(b[1]));
}
__device__ __forceinline__ void mma16816h(float* d, const uint32_t* a, const uint32_t* b) {
    asm volatile("mma.sync.aligned.m16n8k16.row.col.f32.f16.f16.f32 "
        "{%0,%1,%2,%3},{%4,%5,%6,%7},{%8,%9},{%0,%1,%2,%3};"
        : "+f"(d[0]), "+f"(d[1]), "+f"(d[2]), "+f"(d[3])
        : "r"(a[0]), "r"(a[1]), "r"(a[2]), "r"(a[3]), "r"(b[0]), "r"(b[1]));
}
__device__ __forceinline__ uint32_t swq(int r, int q) { return (uint32_t)(q ^ ((r + (r >> 2)) & 3)); }

// ===== dense bf16 6-term mma_gemm (unchanged) =====
#define MG_STAGE 49152
#define MG_SMEM  (2*MG_STAGE)
__global__ __launch_bounds__(256) void mma_gemm(
    const __nv_bfloat16* __restrict__ A0, const __nv_bfloat16* __restrict__ A1,
    const __nv_bfloat16* __restrict__ A2, const __nv_bfloat16* __restrict__ B0,
    const __nv_bfloat16* __restrict__ B1, const __nv_bfloat16* __restrict__ B2,
    float* __restrict__ C, const float* __restrict__ bias,
    __nv_bfloat16* __restrict__ o0, __nv_bfloat16* __restrict__ o1,
    __nv_bfloat16* __restrict__ o2, int K, int N, int relu)
{
    extern __shared__ __align__(128) char smem[];
    uint32_t sbase = s2u(smem);
    int tid = threadIdx.x, lane = tid & 31, wid = tid >> 5;
    int tm = blockIdx.y * 128, tn = blockIdx.x * 128;
    int wm = (wid >> 2) * 64, wn = (wid & 3) * 32;
    const __nv_bfloat16* Ap[3] = {A0, A1, A2};
    const __nv_bfloat16* Bp[3] = {B0, B1, B2};
    float acc[4][4][4];
#pragma unroll
    for (int a = 0; a < 4; a++)
#pragma unroll
        for (int b = 0; b < 4; b++)
#pragma unroll
            for (int c = 0; c < 4; c++) acc[a][b][c] = 0.f;
    auto load = [&](int c) {
        int kc = c * 32;
        uint32_t sb = sbase + (c & 1) * MG_STAGE;
#pragma unroll
        for (int i = 0; i < 12; i++) {
            int f = tid + i * 256;
            int comp = f >> 9, idx = f & 511;
            int r = idx >> 2, q = idx & 3;
            const __nv_bfloat16* src = (comp < 3)
                ? Ap[comp] + (size_t)(tm + r) * K + kc + q * 8
                : Bp[comp - 3] + (size_t)(tn + r) * K + kc + q * 8;
            uint32_t dst = sb + comp * 8192 + r * 64 + (swq(r, q) << 4);
            asm volatile("cp.async.cg.shared.global [%0],[%1],16;" :: "r"(dst), "l"(src));
        }
        asm volatile("cp.async.commit_group;" ::: "memory");
    };
    int nc = K >> 5;
    load(0);
    for (int c = 0; c < nc; c++) {
        if (c + 1 < nc) { load(c + 1); asm volatile("cp.async.wait_group 1;" ::: "memory"); }
        else asm volatile("cp.async.wait_group 0;" ::: "memory");
        __syncthreads();
        uint32_t sb = sbase + (c & 1) * MG_STAGE;
#pragma unroll
        for (int ks = 0; ks < 2; ks++) {
            uint32_t bf[3][8];
#pragma unroll
            for (int bc = 0; bc < 3; bc++)
#pragma unroll
                for (int h = 0; h < 2; h++) {
                    int mat = lane >> 3;
                    int n = wn + h * 16 + (mat >> 1) * 8 + (lane & 7);
                    int kq = ks * 2 + (mat & 1);
                    ldsm4(&bf[bc][h * 4], sb + (3 + bc) * 8192 + n * 64 + (swq(n, kq) << 4));
                }
#pragma unroll
            for (int ac = 0; ac < 3; ac++) {
                uint32_t af[16];
#pragma unroll
                for (int mt = 0; mt < 4; mt++) {
                    int mat = lane >> 3;
                    int row = wm + mt * 16 + (mat & 1) * 8 + (lane & 7);
                    int kq = ks * 2 + (mat >> 1);
                    ldsm4(&af[mt * 4], sb + ac * 8192 + row * 64 + (swq(row, kq) << 4));
                }
#pragma unroll
                for (int bc = 0; bc < 3 - ac; bc++)
#pragma unroll
                    for (int mt = 0; mt < 4; mt++)
#pragma unroll
                        for (int nt = 0; nt < 4; nt++)
                            mma16816(acc[mt][nt], &af[mt * 4],
                                     &bf[bc][(nt >> 1) * 4 + (nt & 1) * 2]);
            }
        }
        __syncthreads();
    }
    int r0 = lane >> 2, c0 = (lane & 3) * 2;
    float* Cs = (float*)smem;
#pragma unroll
    for (int mt = 0; mt < 4; mt++)
#pragma unroll
        for (int i = 0; i < 2; i++) {
            int rl = wm + mt * 16 + r0 + i * 8;
            int row = tm + rl;
#pragma unroll
            for (int nt = 0; nt < 4; nt++) {
                int cl = wn + nt * 8 + c0;
                int col = tn + cl;
                float v0 = acc[mt][nt][i * 2 + 0] + bias[col];
                float v1 = acc[mt][nt][i * 2 + 1] + bias[col + 1];
                if (relu) { v0 = fmaxf(v0, 0.f); v1 = fmaxf(v1, 0.f); }
                if (C) *(float2*)&C[(size_t)row * N + col] = make_float2(v0, v1);
                if (o0) { Cs[rl * 132 + cl] = v0; Cs[rl * 132 + cl + 1] = v1; }
            }
        }
    if (o0) {
        __syncthreads();
#pragma unroll 1
        for (int it = 0; it < 64; it++) {
            int idx = it * 256 + tid;
            int r = idx >> 7, cl = idx & 127;
            size_t g = (size_t)(tm + r) * N + tn + cl;
            split3(Cs[r * 132 + cl], o0[g], o1[g], o2[g]);
        }
    }
}

// ===== dense fp16 3-term mma_gemm (MLP path) =====
#define MGH_STAGE 32768
#define MGH_SMEM  67584   // max(2*32768, 128*132*4)
__global__ __launch_bounds__(256) void mma_gemm_h(
    const __half* __restrict__ A0, const __half* __restrict__ A1,
    const __half* __restrict__ B0, const __half* __restrict__ B1,
    float* __restrict__ C, const float* __restrict__ bias,
    __half* __restrict__ o0, __half* __restrict__ o1, int K, int N, int relu)
{
    extern __shared__ __align__(128) char smem[];
    uint32_t sbase = s2u(smem);
    int tid = threadIdx.x, lane = tid & 31, wid = tid >> 5;
    int tm = blockIdx.y * 128, tn = blockIdx.x * 128;
    int wm = (wid >> 2) * 64, wn = (wid & 3) * 32;
    const __half* Ap[2] = {A0, A1};
    const __half* Bp[2] = {B0, B1};
    float acc[4][4][4];
#pragma unroll
    for (int a = 0; a < 4; a++)
#pragma unroll
        for (int b = 0; b < 4; b++)
#pragma unroll
            for (int c = 0; c < 4; c++) acc[a][b][c] = 0.f;
    auto load = [&](int c) {
        int kc = c * 32;
        uint32_t sb = sbase + (c & 1) * MGH_STAGE;
#pragma unroll
        for (int i = 0; i < 8; i++) {
            int f = tid + i * 256;
            int comp = f >> 9, idx = f & 511;
            int r = idx >> 2, q = idx & 3;
            const __half* src = (comp < 2)
                ? Ap[comp] + (size_t)(tm + r) * K + kc + q * 8
                : Bp[comp - 2] + (size_t)(tn + r) * K + kc + q * 8;
            uint32_t dst = sb + comp * 8192 + r * 64 + (swq(r, q) << 4);
            asm volatile("cp.async.cg.shared.global [%0],[%1],16;" :: "r"(dst), "l"(src));
        }
        asm volatile("cp.async.commit_group;" ::: "memory");
    };
    int nc = K >> 5;
    load(0);
    for (int c = 0; c < nc; c++) {
        if (c + 1 < nc) { load(c + 1); asm volatile("cp.async.wait_group 1;" ::: "memory"); }
        else asm volatile("cp.async.wait_group 0;" ::: "memory");
        __syncthreads();
        uint32_t sb = sbase + (c & 1) * MGH_STAGE;
#pragma unroll
        for (int ks = 0; ks < 2; ks++) {
            uint32_t bf[2][8];
#pragma unroll
            for (int bc = 0; bc < 2; bc++)
#pragma unroll
                for (int h = 0; h < 2; h++) {
                    int mat = lane >> 3;
                    int n = wn + h * 16 + (mat >> 1) * 8 + (lane & 7);
                    int kq = ks * 2 + (mat & 1);
                    ldsm4(&bf[bc][h * 4], sb + (2 + bc) * 8192 + n * 64 + (swq(n, kq) << 4));
                }
#pragma unroll
            for (int ac = 0; ac < 2; ac++) {
                uint32_t af[16];
#pragma unroll
                for (int mt = 0; mt < 4; mt++) {
                    int mat = lane >> 3;
                    int row = wm + mt * 16 + (mat & 1) * 8 + (lane & 7);
                    int kq = ks * 2 + (mat >> 1);
                    ldsm4(&af[mt * 4], sb + ac * 8192 + row * 64 + (swq(row, kq) << 4));
                }
                int nbc = (ac == 0) ? 2 : 1;   // terms: a0b0, a0b1, a1b0
#pragma unroll
                for (int bc = 0; bc < 2; bc++) {
                    if (bc >= nbc) break;
#pragma unroll
                    for (int mt = 0; mt < 4; mt++)
#pragma unroll
                        for (int nt = 0; nt < 4; nt++)
                            mma16816h(acc[mt][nt], &af[mt * 4],
                                      &bf[bc][(nt >> 1) * 4 + (nt & 1) * 2]);
                }
            }
        }
        __syncthreads();
    }
    int r0 = lane >> 2, c0 = (lane & 3) * 2;
    float* Cs = (float*)smem;
#pragma unroll
    for (int mt = 0; mt < 4; mt++)
#pragma unroll
        for (int i = 0; i < 2; i++) {
            int rl = wm + mt * 16 + r0 + i * 8;
            int row = tm + rl;
#pragma unroll
            for (int nt = 0; nt < 4; nt++) {
                int cl = wn + nt * 8 + c0;
                int col = tn + cl;
                float v0 = acc[mt][nt][i * 2 + 0] + bias[col];
                float v1 = acc[mt][nt][i * 2 + 1] + bias[col + 1];
                if (relu) { v0 = fmaxf(v0, 0.f); v1 = fmaxf(v1, 0.f); }
                if (C) *(float2*)&C[(size_t)row * N + col] = make_float2(v0, v1);
                if (o0) { Cs[rl * 132 + cl] = v0; Cs[rl * 132 + cl + 1] = v1; }
            }
        }
    if (o0) {
        __syncthreads();
#pragma unroll 1
        for (int it = 0; it < 64; it++) {
            int idx = it * 256 + tid;
            int r = idx >> 7, cl = idx & 127;
            size_t g = (size_t)(tm + r) * N + tn + cl;
            split2h(Cs[r * 132 + cl], o0[g], o1[g]);
        }
    }
}

// ===== batched scores MMA (unchanged) =====
#define SC_SMEM (6*16384)
__global__ __launch_bounds__(256) void mma_scores(
    const __nv_bfloat16* __restrict__ Q0, const __nv_bfloat16* __restrict__ Q1,
    const __nv_bfloat16* __restrict__ Q2, const __nv_bfloat16* __restrict__ K0,
    const __nv_bfloat16* __restrict__ K1, const __nv_bfloat16* __restrict__ K2,
    float* __restrict__ sc, int l)
{
    extern __shared__ __align__(128) char smem[];
    uint32_t sbase = s2u(smem);
    int tid = threadIdx.x, lane = tid & 31, wid = tid >> 5;
    int z = blockIdx.z, b = z >> 3, h = z & 7;
    int tm = blockIdx.y * 128, tn = blockIdx.x * 128;
    int wm = (wid >> 2) * 64, wn = (wid & 3) * 32;
    const __nv_bfloat16* Qp[3] = {Q0, Q1, Q2};
    const __nv_bfloat16* Kp[3] = {K0, K1, K2};
    size_t qoff = (size_t)(b * 512 + tm) * NHD + h * 64;
    size_t koff = (size_t)(b * 512 + tn) * KVN + l * 512 + h * 64;
#pragma unroll
    for (int i = 0; i < 24; i++) {
        int f = tid + i * 256;
        int comp = f >> 10, idx = f & 1023;
        int r = idx >> 3, q = idx & 7;
        const __nv_bfloat16* src = (comp < 3)
            ? Qp[comp] + qoff + (size_t)r * NHD + q * 8
            : Kp[comp - 3] + koff + (size_t)r * KVN + q * 8;
        uint32_t dst = sbase + comp * 16384 + r * 128 + ((uint32_t)(q ^ (r & 7)) << 4);
        asm volatile("cp.async.cg.shared.global [%0],[%1],16;" :: "r"(dst), "l"(src));
    }
    asm volatile("cp.async.commit_group;" ::: "memory");
    asm volatile("cp.async.wait_group 0;" ::: "memory");
    __syncthreads();
    float acc[4][4][4];
#pragma unroll
    for (int a = 0; a < 4; a++)
#pragma unroll
        for (int bb = 0; bb < 4; bb++)
#pragma unroll
            for (int c = 0; c < 4; c++) acc[a][bb][c] = 0.f;
#pragma unroll
    for (int ks = 0; ks < 4; ks++) {
        uint32_t bf[3][8];
#pragma unroll
        for (int bc = 0; bc < 3; bc++)
#pragma unroll
            for (int hh = 0; hh < 2; hh++) {
                int mat = lane >> 3;
                int n = wn + hh * 16 + (mat >> 1) * 8 + (lane & 7);
                int kq = ks * 2 + (mat & 1);
                ldsm4(&bf[bc][hh * 4], sbase + (3 + bc) * 16384 + n * 128 + ((uint32_t)(kq ^ (n & 7)) << 4));
            }
#pragma unroll
        for (int ac = 0; ac < 3; ac++) {
            uint32_t af[16];
#pragma unroll
            for (int mt = 0; mt < 4; mt++) {
                int mat = lane >> 3;
                int row = wm + mt * 16 + (mat & 1) * 8 + (lane & 7);
                int kq = ks * 2 + (mat >> 1);
                ldsm4(&af[mt * 4], sbase + ac * 16384 + row * 128 + ((uint32_t)(kq ^ (row & 7)) << 4));
            }
#pragma unroll
            for (int bc = 0; bc < 3 - ac; bc++)
#pragma unroll
                for (int mt = 0; mt < 4; mt++)
#pragma unroll
                    for (int nt = 0; nt < 4; nt++)
                        mma16816(acc[mt][nt], &af[mt * 4], &bf[bc][(nt >> 1) * 4 + (nt & 1) * 2]);
        }
    }
    int r0 = lane >> 2, c0 = (lane & 3) * 2;
    float* scz = sc + (size_t)z * NV * NV;
#pragma unroll
    for (int mt = 0; mt < 4; mt++)
#pragma unroll
        for (int i = 0; i < 2; i++) {
            int row = tm + wm + mt * 16 + r0 + i * 8;
#pragma unroll
            for (int nt = 0; nt < 4; nt++) {
                int col = tn + wn + nt * 8 + c0;
                *(float2*)&scz[(size_t)row * NV + col] = make_float2(
                    acc[mt][nt][i * 2 + 0] * 0.125f, acc[mt][nt][i * 2 + 1] * 0.125f);
            }
        }
}

// ===== batched ctx MMA (unchanged) =====
#define CT_STAGE 73728
#define CT_SMEM (2*CT_STAGE)
__global__ __launch_bounds__(256) void mma_ctx(
    const __nv_bfloat16* __restrict__ P0, const __nv_bfloat16* __restrict__ P1,
    const __nv_bfloat16* __restrict__ P2, const __nv_bfloat16* __restrict__ V0,
    const __nv_bfloat16* __restrict__ V1, const __nv_bfloat16* __restrict__ V2,
    float* __restrict__ C, int l)
{
    extern __shared__ __align__(128) char smem[];
    uint32_t sbase = s2u(smem);
    int tid = threadIdx.x, lane = tid & 31, wid = tid >> 5;
    int z = blockIdx.z, b = z >> 3, h = z & 7;
    int tm = blockIdx.y * 128;
    int wm = (wid >> 1) * 32, wn = (wid & 1) * 32;
    const __nv_bfloat16* Pp[3] = {P0, P1, P2};
    const __nv_bfloat16* Vp[3] = {V0, V1, V2};
    size_t poff = ((size_t)z * 512 + tm) * 512;
    size_t voff = (size_t)(b * 512) * KVN + l * 512 + h * 64;
    float acc[2][4][4];
#pragma unroll
    for (int a = 0; a < 2; a++)
#pragma unroll
        for (int bb = 0; bb < 4; bb++)
#pragma unroll
            for (int c = 0; c < 4; c++) acc[a][bb][c] = 0.f;
    auto load = [&](int c) {
        int kc = c * 64;
        uint32_t sb = sbase + (c & 1) * CT_STAGE;
#pragma unroll
        for (int i = 0; i < 18; i++) {
            int f = tid + i * 256;
            if (f < 3072) {
                int comp = f >> 10, idx = f & 1023;
                int r = idx >> 3, q = idx & 7;
                const __nv_bfloat16* src = Pp[comp] + poff + (size_t)r * 512 + kc + q * 8;
                uint32_t dst = sb + comp * 16384 + r * 128 + ((uint32_t)(q ^ (r & 7)) << 4);
                asm volatile("cp.async.cg.shared.global [%0],[%1],16;" :: "r"(dst), "l"(src));
            } else {
                int g = f - 3072;
                int comp = g >> 9, idx = g & 511;
                int kr = idx >> 3, q = idx & 7;
                const __nv_bfloat16* src = Vp[comp] + voff + (size_t)(kc + kr) * KVN + q * 8;
                uint32_t dst = sb + 49152 + comp * 8192 + kr * 128 + ((uint32_t)(q ^ (kr & 7)) << 4);
                asm volatile("cp.async.cg.shared.global [%0],[%1],16;" :: "r"(dst), "l"(src));
            }
        }
        asm volatile("cp.async.commit_group;" ::: "memory");
    };
    load(0);
    for (int c = 0; c < 8; c++) {
        if (c + 1 < 8) { load(c + 1); asm volatile("cp.async.wait_group 1;" ::: "memory"); }
        else asm volatile("cp.async.wait_group 0;" ::: "memory");
        __syncthreads();
        uint32_t sb = sbase + (c & 1) * CT_STAGE;
#pragma unroll
        for (int ks = 0; ks < 4; ks++) {
            uint32_t bf[3][8];
#pragma unroll
            for (int bc = 0; bc < 3; bc++)
#pragma unroll
                for (int j = 0; j < 2; j++) {
                    int krow = ks * 16 + (lane & 15);
                    int qn = ((wn + j * 16) >> 3) + (lane >> 4);
                    ldsm4t(&bf[bc][j * 4],
                           sb + 49152 + bc * 8192 + krow * 128 + ((uint32_t)(qn ^ (krow & 7)) << 4));
                }
#pragma unroll
            for (int ac = 0; ac < 3; ac++) {
                uint32_t af[8];
#pragma unroll
                for (int mt = 0; mt < 2; mt++) {
                    int mat = lane >> 3;
                    int row = wm + mt * 16 + (mat & 1) * 8 + (lane & 7);
                    int kq = ks * 2 + (mat >> 1);
                    ldsm4(&af[mt * 4], sb + ac * 16384 + row * 128 + ((uint32_t)(kq ^ (row & 7)) << 4));
                }
#pragma unroll
                for (int bc = 0; bc < 3 - ac; bc++)
#pragma unroll
                    for (int mt = 0; mt < 2; mt++)
#pragma unroll
                        for (int nt = 0; nt < 4; nt++)
                            mma16816(acc[mt][nt], &af[mt * 4], &bf[bc][(nt >> 1) * 4 + (nt & 1) * 2]);
            }
        }
        __syncthreads();
    }
    int r0 = lane >> 2, c0 = (lane & 3) * 2;
#pragma unroll
    for (int mt = 0; mt < 2; mt++)
#pragma unroll
        for (int i = 0; i < 2; i++) {
            int row = b * 512 + tm + wm + mt * 16 + r0 + i * 8;
#pragma unroll
            for (int nt = 0; nt < 4; nt++) {
                int col = h * 64 + wn + nt * 8 + c0;
                *(float2*)&C[(size_t)row * NHD + col] =
                    make_float2(acc[mt][nt][i * 2 + 0], acc[mt][nt][i * 2 + 1]);
            }
        }
}

// ===== softmax (emits bf16 splits of probs) =====
__global__ __launch_bounds__(256) void softmax512_split(
    const float* __restrict__ x, __nv_bfloat16* __restrict__ p0,
    __nv_bfloat16* __restrict__ p1, __nv_bfloat16* __restrict__ p2, int nrows)
{
    int gw = (blockIdx.x*256 + threadIdx.x) >> 5;
    if (gw >= nrows) return;
    int lane = threadIdx.x & 31;
    const float* row = x + (size_t)gw*512;
    float v[16], m = -3.4e38f;
#pragma unroll
    for (int i=0;i<16;i++){ v[i]=row[lane+32*i]; m=fmaxf(m,v[i]); }
#pragma unroll
    for (int o=16;o;o>>=1) m = fmaxf(m, __shfl_xor_sync(0xffffffffu,m,o));
    float s = 0.f;
#pragma unroll
    for (int i=0;i<16;i++){ v[i]=expf(v[i]-m); s+=v[i]; }
#pragma unroll
    for (int o=16;o;o>>=1) s += __shfl_xor_sync(0xffffffffu,s,o);
    float inv = 1.f/s;
#pragma unroll
    for (int i=0;i<16;i++) {
        size_t idx = (size_t)gw*512 + lane + 32*i;
        split3(v[i]*inv, p0[idx], p1[idx], p2[idx]);
    }
}

// ===== add + layernorm: bf16-3 splits (attention Q path) =====
__global__ __launch_bounds__(256) void add_ln_kernel(
    float* __restrict__ att, const float* __restrict__ d,
    const float* __restrict__ g, const float* __restrict__ b, int nrows,
    __nv_bfloat16* __restrict__ o0, __nv_bfloat16* __restrict__ o1,
    __nv_bfloat16* __restrict__ o2)
{
    int gw = (blockIdx.x*256 + threadIdx.x) >> 5;
    if (gw >= nrows) return;
    int lane = threadIdx.x & 31;
    float* row = att + (size_t)gw*512;
    const float* dr = d + (size_t)gw*512;
    float v[16], s = 0.f;
#pragma unroll
    for (int i=0;i<16;i++){ v[i]=row[lane+32*i]+dr[lane+32*i]; s+=v[i]; }
#pragma unroll
    for (int o=16;o;o>>=1) s += __shfl_xor_sync(0xffffffffu,s,o);
    float mean = s*(1.f/512.f), q = 0.f;
#pragma unroll
    for (int i=0;i<16;i++){ float e=v[i]-mean; q+=e*e; }
#pragma unroll
    for (int o=16;o;o>>=1) q += __shfl_xor_sync(0xffffffffu,q,o);
    float inv = rsqrtf(q*(1.f/512.f) + 1e-5f);
#pragma unroll
    for (int i=0;i<16;i++){
        int c = lane+32*i;
        float val = (v[i]-mean)*inv*g[c]+b[c];
        row[c] = val;
        size_t idx = (size_t)gw*512 + c;
        split3(val, o0[idx], o1[idx], o2[idx]);
    }
}
// ===== add + layernorm: fp16-2 splits (MLP input path) =====
__global__ __launch_bounds__(256) void add_ln_h_kernel(
    float* __restrict__ att, const float* __restrict__ d,
    const float* __restrict__ g, const float* __restrict__ b, int nrows,
    __half* __restrict__ o0, __half* __restrict__ o1)
{
    int gw = (blockIdx.x*256 + threadIdx.x) >> 5;
    if (gw >= nrows) return;
    int lane = threadIdx.x & 31;
    float* row = att + (size_t)gw*512;
    const float* dr = d + (size_t)gw*512;
    float v[16], s = 0.f;
#pragma unroll
    for (int i=0;i<16;i++){ v[i]=row[lane+32*i]+dr[lane+32*i]; s+=v[i]; }
#pragma unroll
    for (int o=16;o;o>>=1) s += __shfl_xor_sync(0xffffffffu,s,o);
    float mean = s*(1.f/512.f), q = 0.f;
#pragma unroll
    for (int i=0;i<16;i++){ float e=v[i]-mean; q+=e*e; }
#pragma unroll
    for (int o=16;o;o>>=1) q += __shfl_xor_sync(0xffffffffu,q,o);
    float inv = rsqrtf(q*(1.f/512.f) + 1e-5f);
#pragma unroll
    for (int i=0;i<16;i++){
        int c = lane+32*i;
        float val = (v[i]-mean)*inv*g[c]+b[c];
        row[c] = val;
        size_t idx = (size_t)gw*512 + c;
        split2h(val, o0[idx], o1[idx]);
    }
}

// ===== sampling (exact JAX threefry, accurate logf) =====
__device__ __forceinline__ void tf2x32(uint32_t k0, uint32_t k1, uint32_t x0, uint32_t x1,
                                       uint32_t& o0, uint32_t& o1)
{
    uint32_t k2 = k0 ^ k1 ^ 0x1BD11BDAu;
    x0 += k0; x1 += k1;
#define TFR(R) { x0 += x1; x1 = __funnelshift_l(x1,x1,R); x1 ^= x0; }
    TFR(13) TFR(15) TFR(26) TFR(6)
    x0 += k1; x1 += k2 + 1u;
    TFR(17) TFR(29) TFR(16) TFR(24)
    x0 += k2; x1 += k0 + 2u;
    TFR(13) TFR(15) TFR(26) TFR(6)
    x0 += k0; x1 += k1 + 3u;
    TFR(17) TFR(29) TFR(16) TFR(24)
    x0 += k1; x1 += k2 + 4u;
    TFR(13) TFR(15) TFR(26) TFR(6)
    x0 += k2; x1 += k0 + 5u;
#undef TFR
    o0 = x0; o1 = x1;
}
__device__ __forceinline__ uint32_t rbits32(uint32_t k0, uint32_t k1, uint32_t i)
{
    uint32_t o0, o1;
    tf2x32(k0, k1, 0u, i, o0, o1);
    return o0 ^ o1;
}
__global__ __launch_bounds__(256) void sample_kernel(
    const float* __restrict__ logits, float* __restrict__ out,
    uint32_t ck0, uint32_t ck1, uint32_t uk0, uint32_t uk1)
{
    __shared__ float sW[NRES];
    int bv = blockIdx.x, t = threadIdx.x;
    if (t < NRES) sW[t] = expf(-logits[(size_t)bv*NRES + t]);
    __syncthreads();
    int warp = t>>5, lane = t&31;
#pragma unroll 1
    for (int it=0; it<16; it++) {
        int s = warp*16 + it;
        uint32_t p = (uint32_t)bv*128u + (uint32_t)s;
        float best = 3.4e38f; int bi = 0;
#pragma unroll
        for (int rr=0; rr<4; rr++) {
            int r = lane + 32*rr;
            uint32_t bits = rbits32(ck0, ck1, p*128u + (uint32_t)r);
            float u = __uint_as_float((bits >> 9) | 0x3f800000u) - 1.0f;
            u += 1.17549435e-38f;
            float v = (-logf(u)) * sW[r];
            if (v < best) { best = v; bi = r; }
        }
#pragma unroll
        for (int o=16;o;o>>=1) {
            float w = __shfl_down_sync(0xffffffffu,best,o);
            int   j = __shfl_down_sync(0xffffffffu,bi,o);
            if (w < best || (w == best && j < bi)) { best = w; bi = j; }
        }
        if (lane == 0) {
            float u = __uint_as_float((rbits32(uk0, uk1, p) >> 9) | 0x3f800000u) - 1.0f;
            out[p] = ((float)bi + u) * (1.0f/128.0f);
        }
    }
}

// ===== host =====
static inline uint32_t rotl32(uint32_t x,int r){ return (x<<r)|(x>>(32-r)); }
static void tf_host(uint32_t k0,uint32_t k1,uint32_t x0,uint32_t x1,uint32_t&o0,uint32_t&o1)
{
    uint32_t k2 = k0^k1^0x1BD11BDAu;
    x0+=k0; x1+=k1;
#define TFRH(R){ x0+=x1; x1=rotl32(x1,R); x1^=x0; }
    TFRH(13)TFRH(15)TFRH(26)TFRH(6)
    x0+=k1; x1+=k2+1u;
    TFRH(17)TFRH(29)TFRH(16)TFRH(24)
    x0+=k2; x1+=k0+2u;
    TFRH(13)TFRH(15)TFRH(26)TFRH(6)
    x0+=k0; x1+=k1+3u;
    TFRH(17)TFRH(29)TFRH(16)TFRH(24)
    x0+=k1; x1+=k2+4u;
    TFRH(13)TFRH(15)TFRH(26)TFRH(6)
    x0+=k2; x1+=k0+5u;
#undef TFRH
    o0=x0; o1=x1;
}

extern "C" void kernel_launch(void* const* d_in, const int* in_sizes, int n_in,
                              void* d_out, int out_size)
{
    (void)in_sizes; (void)n_in; (void)out_size;
    const float* flow=(const float*)d_in[0];
    const float* Wsh =(const float*)d_in[1];
    const float* bsh =(const float*)d_in[2];
    const float* Wk  =(const float*)d_in[3];
    const float* bk  =(const float*)d_in[4];
    const float* Wv  =(const float*)d_in[5];
    const float* bvv =(const float*)d_in[6];
    const float* l1g =(const float*)d_in[7];
    const float* l1b =(const float*)d_in[8];
    const float* l2g =(const float*)d_in[9];
    const float* l2b =(const float*)d_in[10];
    const float* W1  =(const float*)d_in[11];
    const float* b1  =(const float*)d_in[12];
    const float* W2  =(const float*)d_in[13];
    const float* b2  =(const float*)d_in[14];
    const float* W3  =(const float*)d_in[15];
    const float* b3  =(const float*)d_in[16];
    const float* Wd  =(const float*)d_in[17];
    const float* bd  =(const float*)d_in[18];
    float* out = (float*)d_out;

    float *att,*sc,*ctx,*lg;
    __nv_bfloat16 *qt0,*qt1,*qt2,*kt0,*kt1,*kt2,*vt0,*vt1,*vt2,*ps0,*ps1,*ps2;
    __nv_bfloat16 *am0,*am1,*am2,*bs0,*bs1,*bs2;
    __half *h0,*h1,*i0,*i1,*hw0,*hw1;
    cudaGetSymbolAddress((void**)&att, g_att);
    cudaGetSymbolAddress((void**)&sc,  g_scores);
    cudaGetSymbolAddress((void**)&ctx, g_ctx);
    cudaGetSymbolAddress((void**)&lg,  g_logit);
    cudaGetSymbolAddress((void**)&qt0, g_qt0); cudaGetSymbolAddress((void**)&qt1, g_qt1);
    cudaGetSymbolAddress((void**)&qt2, g_qt2);
    cudaGetSymbolAddress((void**)&kt0, g_kt0); cudaGetSymbolAddress((void**)&kt1, g_kt1);
    cudaGetSymbolAddress((void**)&kt2, g_kt2);
    cudaGetSymbolAddress((void**)&vt0, g_vt0); cudaGetSymbolAddress((void**)&vt1, g_vt1);
    cudaGetSymbolAddress((void**)&vt2, g_vt2);
    cudaGetSymbolAddress((void**)&ps0, g_ps0); cudaGetSymbolAddress((void**)&ps1, g_ps1);
    cudaGetSymbolAddress((void**)&ps2, g_ps2);
    cudaGetSymbolAddress((void**)&am0, g_am0); cudaGetSymbolAddress((void**)&am1, g_am1);
    cudaGetSymbolAddress((void**)&am2, g_am2);
    cudaGetSymbolAddress((void**)&bs0, g_bs0); cudaGetSymbolAddress((void**)&bs1, g_bs1);
    cudaGetSymbolAddress((void**)&bs2, g_bs2);
    cudaGetSymbolAddress((void**)&h0, g_h0); cudaGetSymbolAddress((void**)&h1, g_h1);
    cudaGetSymbolAddress((void**)&i0, g_i0); cudaGetSymbolAddress((void**)&i1, g_i1);
    cudaGetSymbolAddress((void**)&hw0, g_hw0); cudaGetSymbolAddress((void**)&hw1, g_hw1);

    static int smem_set = 0;
    if (!smem_set) {
        cudaFuncSetAttribute(mma_gemm,   cudaFuncAttributeMaxDynamicSharedMemorySize, MG_SMEM);
        cudaFuncSetAttribute(mma_gemm_h, cudaFuncAttributeMaxDynamicSharedMemorySize, MGH_SMEM);
        cudaFuncSetAttribute(mma_scores, cudaFuncAttributeMaxDynamicSharedMemorySize, SC_SMEM);
        cudaFuncSetAttribute(mma_ctx,    cudaFuncAttributeMaxDynamicSharedMemorySize, CT_SMEM);
        smem_set = 1;
    }

    uint32_t k1a,k1b,k2a,k2b;
    tf_host(0u,1u,0u,0u,k1a,k1b);
    tf_host(0u,1u,0u,1u,k2a,k2b);

    auto tcg = [&](const __nv_bfloat16* a0,const __nv_bfloat16* a1,const __nv_bfloat16* a2,
                   long long boff, float* C, const float* bias,
                   __nv_bfloat16* o0, __nv_bfloat16* o1, __nv_bfloat16* o2,
                   int K, int N, int relu) {
        dim3 grid(N/128, MTOK/128);
        mma_gemm<<<grid,256,MG_SMEM>>>(a0,a1,a2, bs0+boff,bs1+boff,bs2+boff,
                                       C,bias,o0,o1,o2,K,N,relu);
    };
    auto tcgh = [&](const __half* a0,const __half* a1, long long boff,
                    float* C, const float* bias, __half* o0, __half* o1,
                    int K, int N, int relu) {
        dim3 grid(N/128, MTOK/128);
        mma_gemm_h<<<grid,256,MGH_SMEM>>>(a0,a1, hw0+boff,hw1+boff, C,bias,o0,o1,K,N,relu);
    };
    auto wsplit = [&](const float* w, long long off, int R, int C, int batch) {
        dim3 g(C/32, R/32, batch);
        splitT_kernel<<<g,256>>>(w, bs0+off, bs1+off, bs2+off, R, C);
    };
    auto wsplit2h = [&](const float* w, long long off, int R, int C) {
        dim3 g(C/32, R/32, 1);
        splitT2h_kernel<<<g,256>>>(w, hw0+off, hw1+off, R, C);
    };

    // weight splits
    wsplit(Wsh, OFF_SH, ND, NHD, 1);
    wsplit(Wk,  OFF_K,  ND, NDH, NL*NH);
    wsplit(Wv,  OFF_V,  ND, NDH, NL*NH);
    wsplit(Wd,  OFF_WD, NHD, NRES, 1);
    for (int l=0;l<NL;l++) {
        wsplit2h(W1+(long long)l*NHD*NMLP,  HOFF_W1(l), NHD,  NMLP);
        wsplit2h(W2+(long long)l*NMLP*NMLP, HOFF_W2(l), NMLP, NMLP);
        wsplit2h(W3+(long long)l*NMLP*NHD,  HOFF_W3(l), NMLP, NHD);
    }

    // input projections (bf16 6-term, unchanged)
    split3_kernel<<<(MTOK*ND+255)/256,256>>>(flow, am0,am1,am2, MTOK*ND);
    tcg(am0,am1,am2, OFF_SH, att, bsh, qt0,qt1,qt2, ND, NHD, 0);
    tcg(am0,am1,am2, OFF_K,  nullptr, bk,  kt0,kt1,kt2, ND, KVN, 0);
    tcg(am0,am1,am2, OFF_V,  nullptr, bvv, vt0,vt1,vt2, ND, KVN, 0);

    const int NR = NB*NH*NV;
    for (int l=0; l<NL; l++) {
        {
            dim3 g(4,4,NB*NH);
            mma_scores<<<g,256,SC_SMEM>>>(qt0,qt1,qt2, kt0,kt1,kt2, sc, l);
        }
        softmax512_split<<<(NR*32+255)/256,256>>>(sc, ps0,ps1,ps2, NR);
        {
            dim3 g(1,4,NB*NH);
            mma_ctx<<<g,256,CT_SMEM>>>(ps0,ps1,ps2, vt0,vt1,vt2, ctx, l);
        }
        // ln1 -> fp16-2 splits for MLP
        add_ln_h_kernel<<<(MTOK*32+255)/256,256>>>(att, ctx, l1g+l*NHD, l1b+l*NHD, MTOK,
                                                   h0,h1);
        tcgh(h0,h1, HOFF_W1(l), nullptr, b1+(long long)l*NMLP, i0,i1, NHD, NMLP, 1);
        tcgh(i0,i1, HOFF_W2(l), nullptr, b2+(long long)l*NMLP, h0,h1, NMLP, NMLP, 1);
        tcgh(h0,h1, HOFF_W3(l), ctx, b3+(long long)l*NHD, 0,0, NMLP, NHD, 0);
        // ln2 -> bf16-3 splits for next-layer Q / logits
        add_ln_kernel<<<(MTOK*32+255)/256,256>>>(att, ctx, l2g+l*NHD, l2b+l*NHD, MTOK,
                                                 qt0,qt1,qt2);
    }
    tcg(qt0,qt1,qt2, OFF_WD, lg, bd, 0,0,0, NHD, NRES, 0);
    sample_kernel<<<MTOK,256>>>(lg, out, k1a, k1b, k2a, k2b);
}

// round 15
// speedup vs baseline: 2.5384x; 1.1899x over previous
#include <cuda_runtime.h>
#include <cuda_fp16.h>
#include <cstdint>

#define NB 32
#define NV 512
#define ND 256
#define NL 4
#define NH 8
#define NDH 64
#define NHD 512
#define NMLP 1024
#define NRES 128
#define MTOK (NB*NV)
#define KVN (NL*NH*NDH)

__device__ float g_att[MTOK*NHD];
__device__ float g_scores[NB*NH*NV*NV];
__device__ float g_ctx[MTOK*NHD];
__device__ float g_logit[MTOK*NRES];
__device__ __half g_qh0[MTOK*NHD],  g_qh1[MTOK*NHD];
__device__ __half g_kh0[MTOK*KVN],  g_kh1[MTOK*KVN];
__device__ __half g_vh0[MTOK*KVN],  g_vh1[MTOK*KVN];
__device__ __half g_ph0[NB*NH*NV*NV], g_ph1[NB*NH*NV*NV];
__device__ __half g_fh0[MTOK*NMLP], g_fh1[MTOK*NMLP];
__device__ __half g_ih0[MTOK*NMLP], g_ih1[MTOK*NMLP];
#define BS_TOT 9633792
__device__ __half g_hw0[BS_TOT], g_hw1[BS_TOT];
#define OFF_SH 0
#define OFF_K  131072
#define OFF_V  655360
#define OFF_W1(l) (1179648 + (l)*2097152)
#define OFF_W2(l) (OFF_W1(l) + 524288)
#define OFF_W3(l) (OFF_W2(l) + 1048576)
#define OFF_WD 9568256

__device__ __forceinline__ void split2h(float v, __half& a, __half& b)
{
    __half h0 = __float2half_rn(v);
    a = h0; b = __float2half_rn(v - __half2float(h0));
}
__global__ void split2h_kernel(const float* __restrict__ x, __half* __restrict__ o0,
    __half* __restrict__ o1, int n)
{
    int i = blockIdx.x*256 + threadIdx.x;
    if (i >= n) return;
    split2h(x[i], o0[i], o1[i]);
}
// batched tiled transpose-split: per batch z, in = w[z] [R,C] row-major; out[z][c*R+r]
__global__ __launch_bounds__(256) void splitT2h_kernel(
    const float* __restrict__ w, __half* __restrict__ o0, __half* __restrict__ o1,
    int R, int C)
{
    __shared__ float tile[32][33];
    int z = blockIdx.z;
    const float* wz = w + (size_t)z * R * C;
    size_t ob = (size_t)z * R * C;
    int c0 = blockIdx.x * 32, r0 = blockIdx.y * 32;
    int tx = threadIdx.x & 31, ty = threadIdx.x >> 5;
#pragma unroll
    for (int j = 0; j < 4; j++) {
        int r = ty * 4 + j;
        tile[r][tx] = wz[(size_t)(r0 + r) * C + c0 + tx];
    }
    __syncthreads();
#pragma unroll
    for (int j = 0; j < 4; j++) {
        int rr = ty * 4 + j;
        size_t g = ob + (size_t)(c0 + rr) * R + r0 + tx;
        split2h(tile[tx][rr], o0[g], o1[g]);
    }
}

// ===== MMA helpers =====
__device__ __forceinline__ uint32_t s2u(const void* p) {
    uint32_t a;
    asm("{.reg .u64 t; cvta.to.shared.u64 t, %1; cvt.u32.u64 %0, t;}" : "=r"(a) : "l"(p));
    return a;
}
__device__ __forceinline__ void ldsm4(uint32_t* r, uint32_t addr) {
    asm volatile("ldmatrix.sync.aligned.m8n8.x4.shared.b16 {%0,%1,%2,%3},[%4];"
        : "=r"(r[0]), "=r"(r[1]), "=r"(r[2]), "=r"(r[3]) : "r"(addr));
}
__device__ __forceinline__ void ldsm4t(uint32_t* r, uint32_t addr) {
    asm volatile("ldmatrix.sync.aligned.m8n8.x4.trans.shared.b16 {%0,%1,%2,%3},[%4];"
        : "=r"(r[0]), "=r"(r[1]), "=r"(r[2]), "=r"(r[3]) : "r"(addr));
}
__device__ __forceinline__ void mma16816h(float* d, const uint32_t* a, const uint32_t* b) {
    asm volatile("mma.sync.aligned.m16n8k16.row.col.f32.f16.f16.f32 "
        "{%0,%1,%2,%3},{%4,%5,%6,%7},{%8,%9},{%0,%1,%2,%3};"
        : "+f"(d[0]), "+f"(d[1]), "+f"(d[2]), "+f"(d[3])
        : "r"(a[0]), "r"(a[1]), "r"(a[2]), "r"(a[3]), "r"(b[0]), "r"(b[1]));
}
__device__ __forceinline__ uint32_t swq(int r, int q) { return (uint32_t)(q ^ ((r + (r >> 2)) & 3)); }

// ===== dense fp16 3-term GEMM =====
#define MGH_STAGE 32768
#define MGH_SMEM  67584
__global__ __launch_bounds__(256) void mma_gemm_h(
    const __half* __restrict__ A0, const __half* __restrict__ A1,
    const __half* __restrict__ B0, const __half* __restrict__ B1,
    float* __restrict__ C, const float* __restrict__ bias,
    __half* __restrict__ o0, __half* __restrict__ o1, int K, int N, int relu)
{
    extern __shared__ __align__(128) char smem[];
    uint32_t sbase = s2u(smem);
    int tid = threadIdx.x, lane = tid & 31, wid = tid >> 5;
    int tm = blockIdx.y * 128, tn = blockIdx.x * 128;
    int wm = (wid >> 2) * 64, wn = (wid & 3) * 32;
    const __half* Ap[2] = {A0, A1};
    const __half* Bp[2] = {B0, B1};
    float acc[4][4][4];
#pragma unroll
    for (int a = 0; a < 4; a++)
#pragma unroll
        for (int b = 0; b < 4; b++)
#pragma unroll
            for (int c = 0; c < 4; c++) acc[a][b][c] = 0.f;
    auto load = [&](int c) {
        int kc = c * 32;
        uint32_t sb = sbase + (c & 1) * MGH_STAGE;
#pragma unroll
        for (int i = 0; i < 8; i++) {
            int f = tid + i * 256;
            int comp = f >> 9, idx = f & 511;
            int r = idx >> 2, q = idx & 3;
            const __half* src = (comp < 2)
                ? Ap[comp] + (size_t)(tm + r) * K + kc + q * 8
                : Bp[comp - 2] + (size_t)(tn + r) * K + kc + q * 8;
            uint32_t dst = sb + comp * 8192 + r * 64 + (swq(r, q) << 4);
            asm volatile("cp.async.cg.shared.global [%0],[%1],16;" :: "r"(dst), "l"(src));
        }
        asm volatile("cp.async.commit_group;" ::: "memory");
    };
    int nc = K >> 5;
    load(0);
    for (int c = 0; c < nc; c++) {
        if (c + 1 < nc) { load(c + 1); asm volatile("cp.async.wait_group 1;" ::: "memory"); }
        else asm volatile("cp.async.wait_group 0;" ::: "memory");
        __syncthreads();
        uint32_t sb = sbase + (c & 1) * MGH_STAGE;
#pragma unroll
        for (int ks = 0; ks < 2; ks++) {
            uint32_t bf[2][8];
#pragma unroll
            for (int bc = 0; bc < 2; bc++)
#pragma unroll
                for (int h = 0; h < 2; h++) {
                    int mat = lane >> 3;
                    int n = wn + h * 16 + (mat >> 1) * 8 + (lane & 7);
                    int kq = ks * 2 + (mat & 1);
                    ldsm4(&bf[bc][h * 4], sb + (2 + bc) * 8192 + n * 64 + (swq(n, kq) << 4));
                }
#pragma unroll
            for (int ac = 0; ac < 2; ac++) {
                uint32_t af[16];
#pragma unroll
                for (int mt = 0; mt < 4; mt++) {
                    int mat = lane >> 3;
                    int row = wm + mt * 16 + (mat & 1) * 8 + (lane & 7);
                    int kq = ks * 2 + (mat >> 1);
                    ldsm4(&af[mt * 4], sb + ac * 8192 + row * 64 + (swq(row, kq) << 4));
                }
                int nbc = (ac == 0) ? 2 : 1;
#pragma unroll
                for (int bc = 0; bc < 2; bc++) {
                    if (bc >= nbc) break;
#pragma unroll
                    for (int mt = 0; mt < 4; mt++)
#pragma unroll
                        for (int nt = 0; nt < 4; nt++)
                            mma16816h(acc[mt][nt], &af[mt * 4],
                                      &bf[bc][(nt >> 1) * 4 + (nt & 1) * 2]);
                }
            }
        }
        __syncthreads();
    }
    int r0 = lane >> 2, c0 = (lane & 3) * 2;
    float* Cs = (float*)smem;
#pragma unroll
    for (int mt = 0; mt < 4; mt++)
#pragma unroll
        for (int i = 0; i < 2; i++) {
            int rl = wm + mt * 16 + r0 + i * 8;
            int row = tm + rl;
#pragma unroll
            for (int nt = 0; nt < 4; nt++) {
                int cl = wn + nt * 8 + c0;
                int col = tn + cl;
                float v0 = acc[mt][nt][i * 2 + 0] + bias[col];
                float v1 = acc[mt][nt][i * 2 + 1] + bias[col + 1];
                if (relu) { v0 = fmaxf(v0, 0.f); v1 = fmaxf(v1, 0.f); }
                if (C) *(float2*)&C[(size_t)row * N + col] = make_float2(v0, v1);
                if (o0) { Cs[rl * 132 + cl] = v0; Cs[rl * 132 + cl + 1] = v1; }
            }
        }
    if (o0) {
        __syncthreads();
#pragma unroll 1
        for (int it = 0; it < 64; it++) {
            int idx = it * 256 + tid;
            int r = idx >> 7, cl = idx & 127;
            size_t g = (size_t)(tm + r) * N + tn + cl;
            split2h(Cs[r * 132 + cl], o0[g], o1[g]);
        }
    }
}

// ===== batched scores: sc[b,h] = Q @ K^T * 0.125, fp16 3-term, K=64, tile 128x128 =====
#define SCH_SMEM (4*16384)
__global__ __launch_bounds__(256) void mma_scores_h(
    const __half* __restrict__ Q0, const __half* __restrict__ Q1,
    const __half* __restrict__ K0, const __half* __restrict__ K1,
    float* __restrict__ sc, int l)
{
    extern __shared__ __align__(128) char smem[];
    uint32_t sbase = s2u(smem);
    int tid = threadIdx.x, lane = tid & 31, wid = tid >> 5;
    int z = blockIdx.z, b = z >> 3, h = z & 7;
    int tm = blockIdx.y * 128, tn = blockIdx.x * 128;
    int wm = (wid >> 2) * 64, wn = (wid & 3) * 32;
    const __half* Qp[2] = {Q0, Q1};
    const __half* Kp[2] = {K0, K1};
    size_t qoff = (size_t)(b * 512 + tm) * NHD + h * 64;
    size_t koff = (size_t)(b * 512 + tn) * KVN + l * 512 + h * 64;
#pragma unroll
    for (int i = 0; i < 16; i++) {
        int f = tid + i * 256;
        int comp = f >> 10, idx = f & 1023;
        int r = idx >> 3, q = idx & 7;
        const __half* src = (comp < 2)
            ? Qp[comp] + qoff + (size_t)r * NHD + q * 8
            : Kp[comp - 2] + koff + (size_t)r * KVN + q * 8;
        uint32_t dst = sbase + comp * 16384 + r * 128 + ((uint32_t)(q ^ (r & 7)) << 4);
        asm volatile("cp.async.cg.shared.global [%0],[%1],16;" :: "r"(dst), "l"(src));
    }
    asm volatile("cp.async.commit_group;" ::: "memory");
    asm volatile("cp.async.wait_group 0;" ::: "memory");
    __syncthreads();
    float acc[4][4][4];
#pragma unroll
    for (int a = 0; a < 4; a++)
#pragma unroll
        for (int bb = 0; bb < 4; bb++)
#pragma unroll
            for (int c = 0; c < 4; c++) acc[a][bb][c] = 0.f;
#pragma unroll
    for (int ks = 0; ks < 4; ks++) {
        uint32_t bf[2][8];
#pragma unroll
        for (int bc = 0; bc < 2; bc++)
#pragma unroll
            for (int hh = 0; hh < 2; hh++) {
                int mat = lane >> 3;
                int n = wn + hh * 16 + (mat >> 1) * 8 + (lane & 7);
                int kq = ks * 2 + (mat & 1);
                ldsm4(&bf[bc][hh * 4], sbase + (2 + bc) * 16384 + n * 128 + ((uint32_t)(kq ^ (n & 7)) << 4));
            }
#pragma unroll
        for (int ac = 0; ac < 2; ac++) {
            uint32_t af[16];
#pragma unroll
            for (int mt = 0; mt < 4; mt++) {
                int mat = lane >> 3;
                int row = wm + mt * 16 + (mat & 1) * 8 + (lane & 7);
                int kq = ks * 2 + (mat >> 1);
                ldsm4(&af[mt * 4], sbase + ac * 16384 + row * 128 + ((uint32_t)(kq ^ (row & 7)) << 4));
            }
            int nbc = (ac == 0) ? 2 : 1;
#pragma unroll
            for (int bc = 0; bc < 2; bc++) {
                if (bc >= nbc) break;
#pragma unroll
                for (int mt = 0; mt < 4; mt++)
#pragma unroll
                    for (int nt = 0; nt < 4; nt++)
                        mma16816h(acc[mt][nt], &af[mt * 4], &bf[bc][(nt >> 1) * 4 + (nt & 1) * 2]);
            }
        }
    }
    int r0 = lane >> 2, c0 = (lane & 3) * 2;
    float* scz = sc + (size_t)z * NV * NV;
#pragma unroll
    for (int mt = 0; mt < 4; mt++)
#pragma unroll
        for (int i = 0; i < 2; i++) {
            int row = tm + wm + mt * 16 + r0 + i * 8;
#pragma unroll
            for (int nt = 0; nt < 4; nt++) {
                int col = tn + wn + nt * 8 + c0;
                *(float2*)&scz[(size_t)row * NV + col] = make_float2(
                    acc[mt][nt][i * 2 + 0] * 0.125f, acc[mt][nt][i * 2 + 1] * 0.125f);
            }
        }
}

// ===== batched ctx: ctx[b,q,h*64+e] = P @ V, fp16 3-term, K=512, tile 128x64 =====
#define CTH_STAGE 49152
#define CTH_SMEM (2*CTH_STAGE)
__global__ __launch_bounds__(256) void mma_ctx_h(
    const __half* __restrict__ P0, const __half* __restrict__ P1,
    const __half* __restrict__ V0, const __half* __restrict__ V1,
    float* __restrict__ C, int l)
{
    extern __shared__ __align__(128) char smem[];
    uint32_t sbase = s2u(smem);
    int tid = threadIdx.x, lane = tid & 31, wid = tid >> 5;
    int z = blockIdx.z, b = z >> 3, h = z & 7;
    int tm = blockIdx.y * 128;
    int wm = (wid >> 1) * 32, wn = (wid & 1) * 32;
    const __half* Pp[2] = {P0, P1};
    const __half* Vp[2] = {V0, V1};
    size_t poff = ((size_t)z * 512 + tm) * 512;
    size_t voff = (size_t)(b * 512) * KVN + l * 512 + h * 64;
    float acc[2][4][4];
#pragma unroll
    for (int a = 0; a < 2; a++)
#pragma unroll
        for (int bb = 0; bb < 4; bb++)
#pragma unroll
            for (int c = 0; c < 4; c++) acc[a][bb][c] = 0.f;
    auto load = [&](int c) {
        int kc = c * 64;
        uint32_t sb = sbase + (c & 1) * CTH_STAGE;
#pragma unroll
        for (int i = 0; i < 12; i++) {
            int f = tid + i * 256;
            if (f < 2048) {
                int comp = f >> 10, idx = f & 1023;
                int r = idx >> 3, q = idx & 7;
                const __half* src = Pp[comp] + poff + (size_t)r * 512 + kc + q * 8;
                uint32_t dst = sb + comp * 16384 + r * 128 + ((uint32_t)(q ^ (r & 7)) << 4);
                asm volatile("cp.async.cg.shared.global [%0],[%1],16;" :: "r"(dst), "l"(src));
            } else {
                int g = f - 2048;
                int comp = g >> 9, idx = g & 511;
                int kr = idx >> 3, q = idx & 7;
                const __half* src = Vp[comp] + voff + (size_t)(kc + kr) * KVN + q * 8;
                uint32_t dst = sb + 32768 + comp * 8192 + kr * 128 + ((uint32_t)(q ^ (kr & 7)) << 4);
                asm volatile("cp.async.cg.shared.global [%0],[%1],16;" :: "r"(dst), "l"(src));
            }
        }
        asm volatile("cp.async.commit_group;" ::: "memory");
    };
    load(0);
    for (int c = 0; c < 8; c++) {
        if (c + 1 < 8) { load(c + 1); asm volatile("cp.async.wait_group 1;" ::: "memory"); }
        else asm volatile("cp.async.wait_group 0;" ::: "memory");
        __syncthreads();
        uint32_t sb = sbase + (c & 1) * CTH_STAGE;
#pragma unroll
        for (int ks = 0; ks < 4; ks++) {
            uint32_t bf[2][8];
#pragma unroll
            for (int bc = 0; bc < 2; bc++)
#pragma unroll
                for (int j = 0; j < 2; j++) {
                    int krow = ks * 16 + (lane & 15);
                    int qn = ((wn + j * 16) >> 3) + (lane >> 4);
                    ldsm4t(&bf[bc][j * 4],
                           sb + 32768 + bc * 8192 + krow * 128 + ((uint32_t)(qn ^ (krow & 7)) << 4));
                }
#pragma unroll
            for (int ac = 0; ac < 2; ac++) {
                uint32_t af[8];
#pragma unroll
                for (int mt = 0; mt < 2; mt++) {
                    int mat = lane >> 3;
                    int row = wm + mt * 16 + (mat & 1) * 8 + (lane & 7);
                    int kq = ks * 2 + (mat >> 1);
                    ldsm4(&af[mt * 4], sb + ac * 16384 + row * 128 + ((uint32_t)(kq ^ (row & 7)) << 4));
                }
                int nbc = (ac == 0) ? 2 : 1;
#pragma unroll
                for (int bc = 0; bc < 2; bc++) {
                    if (bc >= nbc) break;
#pragma unroll
                    for (int mt = 0; mt < 2; mt++)
#pragma unroll
                        for (int nt = 0; nt < 4; nt++)
                            mma16816h(acc[mt][nt], &af[mt * 4], &bf[bc][(nt >> 1) * 4 + (nt & 1) * 2]);
                }
            }
        }
        __syncthreads();
    }
    int r0 = lane >> 2, c0 = (lane & 3) * 2;
#pragma unroll
    for (int mt = 0; mt < 2; mt++)
#pragma unroll
        for (int i = 0; i < 2; i++) {
            int row = b * 512 + tm + wm + mt * 16 + r0 + i * 8;
#pragma unroll
            for (int nt = 0; nt < 4; nt++) {
                int col = h * 64 + wn + nt * 8 + c0;
                *(float2*)&C[(size_t)row * NHD + col] =
                    make_float2(acc[mt][nt][i * 2 + 0], acc[mt][nt][i * 2 + 1]);
            }
        }
}

// ===== softmax (emits fp16 pair splits of probs) =====
__global__ __launch_bounds__(256) void softmax512_split(
    const float* __restrict__ x, __half* __restrict__ p0, __half* __restrict__ p1, int nrows)
{
    int gw = (blockIdx.x*256 + threadIdx.x) >> 5;
    if (gw >= nrows) return;
    int lane = threadIdx.x & 31;
    const float* row = x + (size_t)gw*512;
    float v[16], m = -3.4e38f;
#pragma unroll
    for (int i=0;i<16;i++){ v[i]=row[lane+32*i]; m=fmaxf(m,v[i]); }
#pragma unroll
    for (int o=16;o;o>>=1) m = fmaxf(m, __shfl_xor_sync(0xffffffffu,m,o));
    float s = 0.f;
#pragma unroll
    for (int i=0;i<16;i++){ v[i]=expf(v[i]-m); s+=v[i]; }
#pragma unroll
    for (int o=16;o;o>>=1) s += __shfl_xor_sync(0xffffffffu,s,o);
    float inv = 1.f/s;
#pragma unroll
    for (int i=0;i<16;i++) {
        size_t idx = (size_t)gw*512 + lane + 32*i;
        split2h(v[i]*inv, p0[idx], p1[idx]);
    }
}

// ===== add + layernorm, emits fp16 pair splits =====
__global__ __launch_bounds__(256) void add_ln_kernel(
    float* __restrict__ att, const float* __restrict__ d,
    const float* __restrict__ g, const float* __restrict__ b, int nrows,
    __half* __restrict__ o0, __half* __restrict__ o1)
{
    int gw = (blockIdx.x*256 + threadIdx.x) >> 5;
    if (gw >= nrows) return;
    int lane = threadIdx.x & 31;
    float* row = att + (size_t)gw*512;
    const float* dr = d + (size_t)gw*512;
    float v[16], s = 0.f;
#pragma unroll
    for (int i=0;i<16;i++){ v[i]=row[lane+32*i]+dr[lane+32*i]; s+=v[i]; }
#pragma unroll
    for (int o=16;o;o>>=1) s += __shfl_xor_sync(0xffffffffu,s,o);
    float mean = s*(1.f/512.f), q = 0.f;
#pragma unroll
    for (int i=0;i<16;i++){ float e=v[i]-mean; q+=e*e; }
#pragma unroll
    for (int o=16;o;o>>=1) q += __shfl_xor_sync(0xffffffffu,q,o);
    float inv = rsqrtf(q*(1.f/512.f) + 1e-5f);
#pragma unroll
    for (int i=0;i<16;i++){
        int c = lane+32*i;
        float val = (v[i]-mean)*inv*g[c]+b[c];
        row[c] = val;
        size_t idx = (size_t)gw*512 + c;
        split2h(val, o0[idx], o1[idx]);
    }
}

// ===== sampling (exact JAX threefry, accurate logf, min-transform) =====
__device__ __forceinline__ void tf2x32(uint32_t k0, uint32_t k1, uint32_t x0, uint32_t x1,
                                       uint32_t& o0, uint32_t& o1)
{
    uint32_t k2 = k0 ^ k1 ^ 0x1BD11BDAu;
    x0 += k0; x1 += k1;
#define TFR(R) { x0 += x1; x1 = __funnelshift_l(x1,x1,R); x1 ^= x0; }
    TFR(13) TFR(15) TFR(26) TFR(6)
    x0 += k1; x1 += k2 + 1u;
    TFR(17) TFR(29) TFR(16) TFR(24)
    x0 += k2; x1 += k0 + 2u;
    TFR(13) TFR(15) TFR(26) TFR(6)
    x0 += k0; x1 += k1 + 3u;
    TFR(17) TFR(29) TFR(16) TFR(24)
    x0 += k1; x1 += k2 + 4u;
    TFR(13) TFR(15) TFR(26) TFR(6)
    x0 += k2; x1 += k0 + 5u;
#undef TFR
    o0 = x0; o1 = x1;
}
__device__ __forceinline__ uint32_t rbits32(uint32_t k0, uint32_t k1, uint32_t i)
{
    uint32_t o0, o1;
    tf2x32(k0, k1, 0u, i, o0, o1);
    return o0 ^ o1;
}
__global__ __launch_bounds__(256) void sample_kernel(
    const float* __restrict__ logits, float* __restrict__ out,
    uint32_t ck0, uint32_t ck1, uint32_t uk0, uint32_t uk1)
{
    __shared__ float sW[NRES];
    int bv = blockIdx.x, t = threadIdx.x;
    if (t < NRES) sW[t] = expf(-logits[(size_t)bv*NRES + t]);
    __syncthreads();
    int warp = t>>5, lane = t&31;
#pragma unroll 1
    for (int it=0; it<16; it++) {
        int s = warp*16 + it;
        uint32_t p = (uint32_t)bv*128u + (uint32_t)s;
        float best = 3.4e38f; int bi = 0;
#pragma unroll
        for (int rr=0; rr<4; rr++) {
            int r = lane + 32*rr;
            uint32_t bits = rbits32(ck0, ck1, p*128u + (uint32_t)r);
            float u = __uint_as_float((bits >> 9) | 0x3f800000u) - 1.0f;
            u += 1.17549435e-38f;
            float v = (-logf(u)) * sW[r];
            if (v < best) { best = v; bi = r; }
        }
#pragma unroll
        for (int o=16;o;o>>=1) {
            float w = __shfl_down_sync(0xffffffffu,best,o);
            int   j = __shfl_down_sync(0xffffffffu,bi,o);
            if (w < best || (w == best && j < bi)) { best = w; bi = j; }
        }
        if (lane == 0) {
            float u = __uint_as_float((rbits32(uk0, uk1, p) >> 9) | 0x3f800000u) - 1.0f;
            out[p] = ((float)bi + u) * (1.0f/128.0f);
        }
    }
}

// ===== host =====
static inline uint32_t rotl32(uint32_t x,int r){ return (x<<r)|(x>>(32-r)); }
static void tf_host(uint32_t k0,uint32_t k1,uint32_t x0,uint32_t x1,uint32_t&o0,uint32_t&o1)
{
    uint32_t k2 = k0^k1^0x1BD11BDAu;
    x0+=k0; x1+=k1;
#define TFRH(R){ x0+=x1; x1=rotl32(x1,R); x1^=x0; }
    TFRH(13)TFRH(15)TFRH(26)TFRH(6)
    x0+=k1; x1+=k2+1u;
    TFRH(17)TFRH(29)TFRH(16)TFRH(24)
    x0+=k2; x1+=k0+2u;
    TFRH(13)TFRH(15)TFRH(26)TFRH(6)
    x0+=k0; x1+=k1+3u;
    TFRH(17)TFRH(29)TFRH(16)TFRH(24)
    x0+=k1; x1+=k2+4u;
    TFRH(13)TFRH(15)TFRH(26)TFRH(6)
    x0+=k2; x1+=k0+5u;
#undef TFRH
    o0=x0; o1=x1;
}

extern "C" void kernel_launch(void* const* d_in, const int* in_sizes, int n_in,
                              void* d_out, int out_size)
{
    (void)in_sizes; (void)n_in; (void)out_size;
    const float* flow=(const float*)d_in[0];
    const float* Wsh =(const float*)d_in[1];
    const float* bsh =(const float*)d_in[2];
    const float* Wk  =(const float*)d_in[3];
    const float* bk  =(const float*)d_in[4];
    const float* Wv  =(const float*)d_in[5];
    const float* bvv =(const float*)d_in[6];
    const float* l1g =(const float*)d_in[7];
    const float* l1b =(const float*)d_in[8];
    const float* l2g =(const float*)d_in[9];
    const float* l2b =(const float*)d_in[10];
    const float* W1  =(const float*)d_in[11];
    const float* b1  =(const float*)d_in[12];
    const float* W2  =(const float*)d_in[13];
    const float* b2  =(const float*)d_in[14];
    const float* W3  =(const float*)d_in[15];
    const float* b3  =(const float*)d_in[16];
    const float* Wd  =(const float*)d_in[17];
    const float* bd  =(const float*)d_in[18];
    float* out = (float*)d_out;

    float *att,*sc,*ctx,*lg;
    __half *qh0,*qh1,*kh0,*kh1,*vh0,*vh1,*ph0,*ph1,*fh0,*fh1,*ih0,*ih1,*hw0,*hw1;
    cudaGetSymbolAddress((void**)&att, g_att);
    cudaGetSymbolAddress((void**)&sc,  g_scores);
    cudaGetSymbolAddress((void**)&ctx, g_ctx);
    cudaGetSymbolAddress((void**)&lg,  g_logit);
    cudaGetSymbolAddress((void**)&qh0, g_qh0); cudaGetSymbolAddress((void**)&qh1, g_qh1);
    cudaGetSymbolAddress((void**)&kh0, g_kh0); cudaGetSymbolAddress((void**)&kh1, g_kh1);
    cudaGetSymbolAddress((void**)&vh0, g_vh0); cudaGetSymbolAddress((void**)&vh1, g_vh1);
    cudaGetSymbolAddress((void**)&ph0, g_ph0); cudaGetSymbolAddress((void**)&ph1, g_ph1);
    cudaGetSymbolAddress((void**)&fh0, g_fh0); cudaGetSymbolAddress((void**)&fh1, g_fh1);
    cudaGetSymbolAddress((void**)&ih0, g_ih0); cudaGetSymbolAddress((void**)&ih1, g_ih1);
    cudaGetSymbolAddress((void**)&hw0, g_hw0); cudaGetSymbolAddress((void**)&hw1, g_hw1);

    static int smem_set = 0;
    if (!smem_set) {
        cudaFuncSetAttribute(mma_gemm_h,   cudaFuncAttributeMaxDynamicSharedMemorySize, MGH_SMEM);
        cudaFuncSetAttribute(mma_scores_h, cudaFuncAttributeMaxDynamicSharedMemorySize, SCH_SMEM);
        cudaFuncSetAttribute(mma_ctx_h,    cudaFuncAttributeMaxDynamicSharedMemorySize, CTH_SMEM);
        smem_set = 1;
    }

    uint32_t k1a,k1b,k2a,k2b;
    tf_host(0u,1u,0u,0u,k1a,k1b);
    tf_host(0u,1u,0u,1u,k2a,k2b);

    auto tcgh = [&](const __half* a0,const __half* a1, long long boff,
                    float* C, const float* bias, __half* o0, __half* o1,
                    int K, int N, int relu) {
        dim3 grid(N/128, MTOK/128);
        mma_gemm_h<<<grid,256,MGH_SMEM>>>(a0,a1, hw0+boff,hw1+boff, C,bias,o0,o1,K,N,relu);
    };
    auto wsplit = [&](const float* w, long long off, int R, int C, int batch) {
        dim3 g(C/32, R/32, batch);
        splitT2h_kernel<<<g,256>>>(w, hw0+off, hw1+off, R, C);
    };

    // weight splits (coalesced transpose, fp16 pairs)
    wsplit(Wsh, OFF_SH, ND, NHD, 1);
    wsplit(Wk,  OFF_K,  ND, NDH, NL*NH);
    wsplit(Wv,  OFF_V,  ND, NDH, NL*NH);
    wsplit(Wd,  OFF_WD, NHD, NRES, 1);
    for (int l=0;l<NL;l++) {
        wsplit(W1+(long long)l*NHD*NMLP,  OFF_W1(l), NHD,  NMLP, 1);
        wsplit(W2+(long long)l*NMLP*NMLP, OFF_W2(l), NMLP, NMLP, 1);
        wsplit(W3+(long long)l*NMLP*NHD,  OFF_W3(l), NMLP, NHD,  1);
    }

    // input projections
    split2h_kernel<<<(MTOK*ND+255)/256,256>>>(flow, fh0,fh1, MTOK*ND);
    tcgh(fh0,fh1, OFF_SH, att, bsh, qh0,qh1, ND, NHD, 0);
    tcgh(fh0,fh1, OFF_K,  nullptr, bk,  kh0,kh1, ND, KVN, 0);
    tcgh(fh0,fh1, OFF_V,  nullptr, bvv, vh0,vh1, ND, KVN, 0);

    const int NR = NB*NH*NV;
    for (int l=0; l<NL; l++) {
        {
            dim3 g(4,4,NB*NH);
            mma_scores_h<<<g,256,SCH_SMEM>>>(qh0,qh1, kh0,kh1, sc, l);
        }
        softmax512_split<<<(NR*32+255)/256,256>>>(sc, ph0,ph1, NR);
        {
            dim3 g(1,4,NB*NH);
            mma_ctx_h<<<g,256,CTH_SMEM>>>(ph0,ph1, vh0,vh1, ctx, l);
        }
        add_ln_kernel<<<(MTOK*32+255)/256,256>>>(att, ctx, l1g+l*NHD, l1b+l*NHD, MTOK,
                                                 fh0,fh1);
        tcgh(fh0,fh1, OFF_W1(l), nullptr, b1+(long long)l*NMLP, ih0,ih1, NHD, NMLP, 1);
        tcgh(ih0,ih1, OFF_W2(l), nullptr, b2+(long long)l*NMLP, fh0,fh1, NMLP, NMLP, 1);
        tcgh(fh0,fh1, OFF_W3(l), ctx, b3+(long long)l*NHD, 0,0, NMLP, NHD, 0);
        add_ln_kernel<<<(MTOK*32+255)/256,256>>>(att, ctx, l2g+l*NHD, l2b+l*NHD, MTOK,
                                                 qh0,qh1);
    }
    tcgh(qh0,qh1, OFF_WD, lg, bd, 0,0, NHD, NRES, 0);
    sample_kernel<<<MTOK,256>>>(lg, out, k1a, k1b, k2a, k2b);
}